// round 1
// baseline (speedup 1.0000x reference)
#include <cuda_runtime.h>

#define BB 2
#define SS 2048
#define DD 2048
#define HH 16
#define HDIM 128
#define MROWS (BB*SS)   // 4096

// Scratch (no cudaMalloc allowed) — 4 x 33.5 MB fp32 buffers.
__device__ float g_q[(size_t)MROWS * DD];
__device__ float g_k[(size_t)MROWS * DD];
__device__ float g_v[(size_t)MROWS * DD];
__device__ float g_attn[(size_t)MROWS * DD];

// ---------------------------------------------------------------------------
// GEMM: C[m,n] = sum_k A[m,k] * W[n,k] + bias[n]   (A:[M,K] row-major,
// W:[N,K] row-major, i.e. torch Linear x @ W^T + b). 128x128x16 tiles,
// 256 threads, 8x8 per thread with stride-16 register mapping.
// ---------------------------------------------------------------------------
__device__ __forceinline__ void gemm_body(
    const float* __restrict__ A, const float* __restrict__ W,
    const float* __restrict__ bias, float* __restrict__ C,
    int K, int N)
{
    __shared__ float As[16][132];
    __shared__ float Bs[16][132];
    const int tid = threadIdx.x;
    const int bm = blockIdx.y * 128;
    const int bn = blockIdx.x * 128;
    const int ty = tid >> 4;       // 0..15
    const int tx = tid & 15;       // 0..15

    float acc[8][8];
#pragma unroll
    for (int i = 0; i < 8; i++)
#pragma unroll
        for (int j = 0; j < 8; j++) acc[i][j] = 0.f;

    const float* Aptr = A + (size_t)bm * K;
    const float* Wptr = W + (size_t)bn * K;

    for (int k0 = 0; k0 < K; k0 += 16) {
#pragma unroll
        for (int u = 0; u < 2; u++) {
            int idx = tid + u * 256;      // 0..511 float4 slots
            int r   = idx >> 2;           // 0..127 tile row
            int c4  = idx & 3;            // 0..3   k-group
            float4 a = *(const float4*)(Aptr + (size_t)r * K + k0 + c4 * 4);
            As[c4*4+0][r] = a.x; As[c4*4+1][r] = a.y;
            As[c4*4+2][r] = a.z; As[c4*4+3][r] = a.w;
            float4 w = *(const float4*)(Wptr + (size_t)r * K + k0 + c4 * 4);
            Bs[c4*4+0][r] = w.x; Bs[c4*4+1][r] = w.y;
            Bs[c4*4+2][r] = w.z; Bs[c4*4+3][r] = w.w;
        }
        __syncthreads();
#pragma unroll
        for (int kk = 0; kk < 16; kk++) {
            float a[8], b[8];
#pragma unroll
            for (int i = 0; i < 8; i++) a[i] = As[kk][ty + 16*i];
#pragma unroll
            for (int j = 0; j < 8; j++) b[j] = Bs[kk][tx + 16*j];
#pragma unroll
            for (int i = 0; i < 8; i++)
#pragma unroll
                for (int j = 0; j < 8; j++)
                    acc[i][j] += a[i] * b[j];
        }
        __syncthreads();
    }

#pragma unroll
    for (int i = 0; i < 8; i++) {
        size_t m = (size_t)(bm + ty + 16*i);
#pragma unroll
        for (int j = 0; j < 8; j++) {
            int n = bn + tx + 16*j;
            C[m * N + n] = acc[i][j] + bias[n];
        }
    }
}

__global__ __launch_bounds__(256) void sgemm_nt_bias(
    const float* __restrict__ A, const float* __restrict__ W,
    const float* __restrict__ bias, float* __restrict__ C,
    int K, int N)
{
    gemm_body(A, W, bias, C, K, N);
}

// Fused QKV: blockIdx.z selects the projection (fills wave tail better).
__global__ __launch_bounds__(256) void sgemm_qkv(
    const float* __restrict__ A,
    const float* __restrict__ Wq, const float* __restrict__ bq, float* __restrict__ Cq,
    const float* __restrict__ Wk, const float* __restrict__ bk, float* __restrict__ Ck,
    const float* __restrict__ Wv, const float* __restrict__ bv, float* __restrict__ Cv,
    int K, int N)
{
    const float* W; const float* b; float* C;
    if (blockIdx.z == 0)      { W = Wq; b = bq; C = Cq; }
    else if (blockIdx.z == 1) { W = Wk; b = bk; C = Ck; }
    else                      { W = Wv; b = bv; C = Cv; }
    gemm_body(A, W, b, C, K, N);
}

// ---------------------------------------------------------------------------
// Flash-attention (fp32, online softmax). One block = 64 queries of one
// (b, h). Tiles: Q 64x128, K 64x128, V 64x128, P 64x64 in smem.
// Thread map: ty=tid/16 tx=tid%16; rows r_i = ty+16i, score cols c_j = tx+16j,
// output dims d_c = tx+16c.
// ---------------------------------------------------------------------------
#define QS_STR 132
#define PS_STR 68
#define SM_FLOATS (3*64*QS_STR + 64*PS_STR + 64)

__global__ __launch_bounds__(256) void attn_kernel(
    const float* __restrict__ qg, const float* __restrict__ kg,
    const float* __restrict__ vg, const int* __restrict__ mask,
    float* __restrict__ og)
{
    extern __shared__ float sm[];
    float* Qs = sm;                       // 64 x 132
    float* Ks = Qs + 64 * QS_STR;         // 64 x 132
    float* Vs = Ks + 64 * QS_STR;         // 64 x 132
    float* Ps = Vs + 64 * QS_STR;         // 64 x 68
    int*   Ms = (int*)(Ps + 64 * PS_STR); // 64

    const int b  = blockIdx.z;
    const int h  = blockIdx.y;
    const int q0 = blockIdx.x * 64;
    const int tid = threadIdx.x;
    const int ty = tid >> 4;
    const int tx = tid & 15;
    const float scale = 0.08838834764831845f; // 1/sqrt(128)

    // Load Q tile (float4, coalesced)
    for (int i = tid; i < 64 * 32; i += 256) {
        int r = i >> 5, c4 = i & 31;
        float4 v = *(const float4*)(qg + (size_t)(b * SS + q0 + r) * DD + h * HDIM + c4 * 4);
        *(float4*)(Qs + r * QS_STR + c4 * 4) = v;
    }

    float mrow[4], lrow[4], acc[4][8];
#pragma unroll
    for (int i = 0; i < 4; i++) {
        mrow[i] = -1e30f; lrow[i] = 0.f;
#pragma unroll
        for (int c = 0; c < 8; c++) acc[i][c] = 0.f;
    }

    for (int k0 = 0; k0 < SS; k0 += 64) {
        __syncthreads();   // protect Ks/Vs/Ps from readers of previous tile
        for (int i = tid; i < 64 * 32; i += 256) {
            int r = i >> 5, c4 = i & 31;
            size_t gb = (size_t)(b * SS + k0 + r) * DD + h * HDIM + c4 * 4;
            *(float4*)(Ks + r * QS_STR + c4 * 4) = *(const float4*)(kg + gb);
            *(float4*)(Vs + r * QS_STR + c4 * 4) = *(const float4*)(vg + gb);
        }
        if (tid < 64) Ms[tid] = mask[b * SS + k0 + tid];
        __syncthreads();

        // S = Q K^T for a 4x4 register sub-tile per thread
        float sv[4][4];
#pragma unroll
        for (int i = 0; i < 4; i++)
#pragma unroll
            for (int j = 0; j < 4; j++) sv[i][j] = 0.f;

        for (int d = 0; d < HDIM; d += 4) {
            float4 qv[4], kv[4];
#pragma unroll
            for (int i = 0; i < 4; i++)
                qv[i] = *(const float4*)(Qs + (ty + 16*i) * QS_STR + d);
#pragma unroll
            for (int j = 0; j < 4; j++)
                kv[j] = *(const float4*)(Ks + (tx + 16*j) * QS_STR + d);
#pragma unroll
            for (int i = 0; i < 4; i++)
#pragma unroll
                for (int j = 0; j < 4; j++)
                    sv[i][j] += qv[i].x * kv[j].x + qv[i].y * kv[j].y
                              + qv[i].z * kv[j].z + qv[i].w * kv[j].w;
        }

        // Online softmax per row (16-lane shfl reductions; lanes of one ty
        // group are contiguous within a warp half)
#pragma unroll
        for (int i = 0; i < 4; i++) {
            float smax = -1e30f;
#pragma unroll
            for (int j = 0; j < 4; j++) {
                float s = sv[i][j] * scale;
                if (Ms[tx + 16*j] == 0) s = -1e9f;
                sv[i][j] = s;
                smax = fmaxf(smax, s);
            }
#pragma unroll
            for (int o = 8; o >= 1; o >>= 1)
                smax = fmaxf(smax, __shfl_xor_sync(0xffffffffu, smax, o));
            float mnew  = fmaxf(mrow[i], smax);
            float alpha = expf(mrow[i] - mnew);
            float rs = 0.f;
#pragma unroll
            for (int j = 0; j < 4; j++) {
                float p = expf(sv[i][j] - mnew);
                Ps[(ty + 16*i) * PS_STR + tx + 16*j] = p;
                rs += p;
            }
#pragma unroll
            for (int o = 8; o >= 1; o >>= 1)
                rs += __shfl_xor_sync(0xffffffffu, rs, o);
            lrow[i] = lrow[i] * alpha + rs;
            mrow[i] = mnew;
#pragma unroll
            for (int c = 0; c < 8; c++) acc[i][c] *= alpha;
        }
        __syncthreads();

        // O += P V
#pragma unroll 4
        for (int j = 0; j < 64; j++) {
            float p0 = Ps[(ty     ) * PS_STR + j];
            float p1 = Ps[(ty + 16) * PS_STR + j];
            float p2 = Ps[(ty + 32) * PS_STR + j];
            float p3 = Ps[(ty + 48) * PS_STR + j];
#pragma unroll
            for (int c = 0; c < 8; c++) {
                float vv = Vs[j * QS_STR + tx + 16*c];
                acc[0][c] += p0 * vv;
                acc[1][c] += p1 * vv;
                acc[2][c] += p2 * vv;
                acc[3][c] += p3 * vv;
            }
        }
    }

#pragma unroll
    for (int i = 0; i < 4; i++) {
        float inv = 1.0f / lrow[i];
        int r = q0 + ty + 16*i;
#pragma unroll
        for (int c = 0; c < 8; c++)
            og[(size_t)(b * SS + r) * DD + h * HDIM + tx + 16*c] = acc[i][c] * inv;
    }
}

// ---------------------------------------------------------------------------
extern "C" void kernel_launch(void* const* d_in, const int* in_sizes, int n_in,
                              void* d_out, int out_size)
{
    const float* hidden = (const float*)d_in[0];
    const int*   mask   = (const int*)  d_in[1];
    const float* Wq = (const float*)d_in[2];
    const float* bq = (const float*)d_in[3];
    const float* Wk = (const float*)d_in[4];
    const float* bk = (const float*)d_in[5];
    const float* Wv = (const float*)d_in[6];
    const float* bv = (const float*)d_in[7];
    const float* Wo = (const float*)d_in[8];
    const float* bo = (const float*)d_in[9];
    float* out = (float*)d_out;

    float *qb, *kb, *vb, *ab;
    cudaGetSymbolAddress((void**)&qb, g_q);
    cudaGetSymbolAddress((void**)&kb, g_k);
    cudaGetSymbolAddress((void**)&vb, g_v);
    cudaGetSymbolAddress((void**)&ab, g_attn);

    dim3 gqkv(DD / 128, MROWS / 128, 3);   // 16 x 32 x 3
    sgemm_qkv<<<gqkv, 256>>>(hidden, Wq, bq, qb, Wk, bk, kb, Wv, bv, vb, DD, DD);

    size_t smem = SM_FLOATS * sizeof(float);   // ~116 KB
    cudaFuncSetAttribute(attn_kernel, cudaFuncAttributeMaxDynamicSharedMemorySize, (int)smem);
    attn_kernel<<<dim3(SS / 64, HH, BB), 256, smem>>>(qb, kb, vb, mask, ab);

    dim3 go(DD / 128, MROWS / 128, 1);
    sgemm_nt_bias<<<go, 256>>>(ab, Wo, bo, out, DD, DD);
}

// round 3
// speedup vs baseline: 2.3912x; 2.3912x over previous
#include <cuda_runtime.h>
#include <cuda_bf16.h>
#include <cstdint>

#define BB 2
#define SS 2048
#define DD 2048
#define HH 16
#define HDIM 128
#define MROWS (BB*SS)     // 4096
#define BH (BB*HH)        // 32

// ---------------------------------------------------------------------------
// Scratch (__device__ globals; cudaMalloc is forbidden)
// ---------------------------------------------------------------------------
__device__ float g_q [(size_t)MROWS * DD];
__device__ float g_k [(size_t)MROWS * DD];
__device__ float g_v [(size_t)MROWS * DD];
__device__ float g_vt[(size_t)MROWS * DD];              // [bh][128][2048]
__device__ float g_attn[(size_t)MROWS * DD];
__device__ float g_scores[(size_t)BH * SS * SS];        // 512 MiB

// ---------------------------------------------------------------------------
// mma.sync helpers (compute_80+, legal under plain sm_103 PTX target)
// ---------------------------------------------------------------------------
__device__ __forceinline__ uint32_t smem_u32_of(const void* p) {
    uint32_t a;
    asm("{ .reg .u64 t; cvta.to.shared.u64 t, %1; cvt.u32.u64 %0, t; }" : "=r"(a) : "l"(p));
    return a;
}

__device__ __forceinline__ void ldsm_x4(uint32_t* r, uint32_t addr) {
    asm volatile("ldmatrix.sync.aligned.m8n8.x4.shared.b16 {%0,%1,%2,%3}, [%4];"
                 : "=r"(r[0]), "=r"(r[1]), "=r"(r[2]), "=r"(r[3]) : "r"(addr));
}

__device__ __forceinline__ void mma_bf16(float* c, const uint32_t* a,
                                         uint32_t b0, uint32_t b1) {
    asm volatile(
        "mma.sync.aligned.m16n8k16.row.col.f32.bf16.bf16.f32 "
        "{%0,%1,%2,%3}, {%4,%5,%6,%7}, {%8,%9}, {%0,%1,%2,%3};"
        : "+f"(c[0]), "+f"(c[1]), "+f"(c[2]), "+f"(c[3])
        : "r"(a[0]), "r"(a[1]), "r"(a[2]), "r"(a[3]), "r"(b0), "r"(b1));
}

__device__ __forceinline__ uint32_t pack_bf16(float x, float y) {
    __nv_bfloat16 a = __float2bfloat16_rn(x);
    __nv_bfloat16 b = __float2bfloat16_rn(y);
    return (uint32_t)__bfloat16_as_ushort(a) | ((uint32_t)__bfloat16_as_ushort(b) << 16);
}

// ---------------------------------------------------------------------------
// GEMM: D[M x N] = A[M x K] * B[N x K]^T (+ bias), fp32 in/out.
// Block tile 128x128, k-tile 32. 512 threads = 16 warps (4x4), warp 32x32.
// bf16 hi/lo split in smem, 3-product compensation, fp32 mma accumulators.
// Smem rows: 32 bf16 = 64B + 16B pad = 80B stride (conflict-free LDSM).
// ---------------------------------------------------------------------------
#define BKT 32
#define ROWB 80
#define S_AHI 0
#define S_ALO 10240
#define S_BHI 20480
#define S_BLO 30720
#define S_STAGE 40960
#define SMEM_BYTES (2 * S_STAGE)    // 81920

template<bool BIAS>
__device__ __forceinline__ void gemm_body(
    const float* __restrict__ A, int lda,
    const float* __restrict__ Bw, int ldb,
    const float* __restrict__ bias,
    float* __restrict__ D, int ldd, int K)
{
    extern __shared__ __align__(1024) char smem[];
    const uint32_t sbase = smem_u32_of(smem);

    const int tid  = threadIdx.x;
    const int wid  = tid >> 5;
    const int lane = tid & 31;
    const int wm = (wid >> 2) * 32;        // warp row offset in tile
    const int wn = (wid & 3)  * 32;        // warp col offset in tile
    const int bm = blockIdx.y * 128;
    const int bn = blockIdx.x * 128;

    float acc[2][4][4];
#pragma unroll
    for (int mf = 0; mf < 2; mf++)
#pragma unroll
        for (int nf = 0; nf < 4; nf++)
#pragma unroll
            for (int e = 0; e < 4; e++) acc[mf][nf][e] = 0.f;

    float4 streg[4];
    // slot mapping: 2048 float4 slots; [0,1024) = A tile, [1024,2048) = B tile
    auto gload = [&](int kt) {
#pragma unroll
        for (int i = 0; i < 4; i++) {
            int slot = tid + i * 512;
            int r  = (slot & 1023) >> 3;
            int c4 = slot & 7;
            const float* gp = (i < 2)
                ? A  + (size_t)(bm + r) * lda + kt * BKT + c4 * 4
                : Bw + (size_t)(bn + r) * ldb + kt * BKT + c4 * 4;
            streg[i] = *(const float4*)gp;
        }
    };
    auto sstore = [&](int s) {
        char* st = smem + s * S_STAGE;
#pragma unroll
        for (int i = 0; i < 4; i++) {
            int slot = tid + i * 512;
            int r  = (slot & 1023) >> 3;
            int c4 = slot & 7;
            char* hb = st + ((i < 2) ? S_AHI : S_BHI);
            char* lb = st + ((i < 2) ? S_ALO : S_BLO);
            float4 v = streg[i];
            float hx = __bfloat162float(__float2bfloat16_rn(v.x));
            float hy = __bfloat162float(__float2bfloat16_rn(v.y));
            float hz = __bfloat162float(__float2bfloat16_rn(v.z));
            float hw = __bfloat162float(__float2bfloat16_rn(v.w));
            uint2 hp = make_uint2(pack_bf16(v.x, v.y), pack_bf16(v.z, v.w));
            uint2 lp = make_uint2(pack_bf16(v.x - hx, v.y - hy),
                                  pack_bf16(v.z - hz, v.w - hw));
            int off = r * ROWB + c4 * 8;
            *(uint2*)(hb + off) = hp;
            *(uint2*)(lb + off) = lp;
        }
    };

    const int NKT = K / BKT;
    gload(0);
    sstore(0);
    __syncthreads();

    // ldmatrix lane addressing
    const int a_row = lane & 15;                              // rows 0..15
    const int a_colB = ((lane >> 4) * 8) * 2;                 // +0 / +16 bytes
    const int b_row = (lane & 7) + ((lane & 16) ? 8 : 0);     // n rows
    const int b_colB = ((lane & 8) ? 8 : 0) * 2;              // k half

    for (int kt = 0; kt < NKT; kt++) {
        const int s = kt & 1;
        if (kt + 1 < NKT) gload(kt + 1);

        const uint32_t sb = sbase + s * S_STAGE;
#pragma unroll
        for (int ks = 0; ks < 2; ks++) {
            uint32_t ah[2][4], al[2][4], bh[2][4], bl[2][4];
            const int kB = ks * 32;   // 16 bf16 = 32 bytes
#pragma unroll
            for (int mf = 0; mf < 2; mf++) {
                uint32_t ad = sb + S_AHI + (wm + mf * 16 + a_row) * ROWB + a_colB + kB;
                ldsm_x4(ah[mf], ad);
                ldsm_x4(al[mf], ad + (S_ALO - S_AHI));
            }
#pragma unroll
            for (int np = 0; np < 2; np++) {
                uint32_t bd = sb + S_BHI + (wn + np * 16 + b_row) * ROWB + b_colB + kB;
                ldsm_x4(bh[np], bd);
                ldsm_x4(bl[np], bd + (S_BLO - S_BHI));
            }
#pragma unroll
            for (int mf = 0; mf < 2; mf++)
#pragma unroll
                for (int np = 0; np < 2; np++)
#pragma unroll
                    for (int h = 0; h < 2; h++) {
                        int nf = np * 2 + h;
                        mma_bf16(acc[mf][nf], ah[mf], bh[np][2*h], bh[np][2*h+1]);
                        mma_bf16(acc[mf][nf], ah[mf], bl[np][2*h], bl[np][2*h+1]);
                        mma_bf16(acc[mf][nf], al[mf], bh[np][2*h], bh[np][2*h+1]);
                    }
        }
        if (kt + 1 < NKT) sstore((kt + 1) & 1);
        __syncthreads();
    }

    // Epilogue: fragment layout -> direct float2 global stores
    const int er = lane >> 2;          // 0..7
    const int ec = (lane & 3) * 2;     // 0,2,4,6
#pragma unroll
    for (int mf = 0; mf < 2; mf++) {
#pragma unroll
        for (int nf = 0; nf < 4; nf++) {
            int gr = bm + wm + mf * 16 + er;
            int gc = bn + wn + nf * 8 + ec;
            float b0 = 0.f, b1 = 0.f;
            if (BIAS) { b0 = bias[gc]; b1 = bias[gc + 1]; }
            float2 v0 = make_float2(acc[mf][nf][0] + b0, acc[mf][nf][1] + b1);
            float2 v1 = make_float2(acc[mf][nf][2] + b0, acc[mf][nf][3] + b1);
            *(float2*)(D + (size_t)gr * ldd + gc) = v0;
            *(float2*)(D + (size_t)(gr + 8) * ldd + gc) = v1;
        }
    }
}

// Generic z-batched wrapper: per-z offsets = (z/16)*zb + (z%16)*zh
template<bool BIAS>
__global__ __launch_bounds__(512, 1) void gemm_tc(
    const float* A, int lda, long long azb, long long azh,
    const float* Bw, int ldb, long long bzb, long long bzh,
    const float* bias,
    float* D, int ldd, long long dzb, long long dzh, int K)
{
    const long long zb = blockIdx.z >> 4, zh = blockIdx.z & 15;
    gemm_body<BIAS>(A + zb * azb + zh * azh, lda,
                    Bw + zb * bzb + zh * bzh, ldb, bias,
                    D + zb * dzb + zh * dzh, ldd, K);
}

// Fused QKV: z in {0,1,2} picks projection
__global__ __launch_bounds__(512, 1) void qkv_tc(
    const float* hidden,
    const float* Wq, const float* bq, float* q,
    const float* Wk, const float* bk, float* k,
    const float* Wv, const float* bv, float* v)
{
    const float* W; const float* b; float* Dp;
    if (blockIdx.z == 0)      { W = Wq; b = bq; Dp = q; }
    else if (blockIdx.z == 1) { W = Wk; b = bk; Dp = k; }
    else                      { W = Wv; b = bv; Dp = v; }
    gemm_body<true>(hidden, DD, W, DD, b, Dp, DD, DD);
}

// ---------------------------------------------------------------------------
// V transpose: v[(b,s), h*128+d] -> vt[(bh*128+d), s]
// ---------------------------------------------------------------------------
__global__ void transpose_v(const float* __restrict__ v, float* __restrict__ vt)
{
    __shared__ float t[32][33];
    const int bh = blockIdx.z;
    const int b = bh >> 4, h = bh & 15;
    const int s0 = blockIdx.x * 32, d0 = blockIdx.y * 32;
    const int tx = threadIdx.x, ty = threadIdx.y;
#pragma unroll
    for (int i = 0; i < 32; i += 8)
        t[ty + i][tx] = v[(size_t)(b * SS + s0 + ty + i) * DD + h * HDIM + d0 + tx];
    __syncthreads();
#pragma unroll
    for (int i = 0; i < 32; i += 8)
        vt[(size_t)(bh * HDIM + d0 + ty + i) * SS + s0 + tx] = t[tx][ty + i];
}

// ---------------------------------------------------------------------------
// Masked softmax (in place, row = (bh, q), width 2048); folds 1/sqrt(HD)
// ---------------------------------------------------------------------------
__global__ __launch_bounds__(256) void softmax_kernel(
    float* __restrict__ sc, const int* __restrict__ mask)
{
    __shared__ float red[8];
    __shared__ int msm[SS];
    const int row = blockIdx.x;
    const int b = row >> 15;              // row = bh*2048 + q ; b = bh/16
    float* p = sc + (size_t)row * SS;
    const int* mk = mask + (size_t)b * SS;
    const int tid = threadIdx.x;
    const int lane = tid & 31, wrp = tid >> 5;
    const float scale = 0.08838834764831845f;

    for (int i = tid; i < SS / 4; i += 256) ((int4*)msm)[i] = ((const int4*)mk)[i];
    __syncthreads();

    float4 v0 = ((const float4*)p)[tid];
    float4 v1 = ((const float4*)p)[tid + 256];
    float x[8] = {v0.x, v0.y, v0.z, v0.w, v1.x, v1.y, v1.z, v1.w};
    const int k0 = tid * 4, k1 = (tid + 256) * 4;
#pragma unroll
    for (int j = 0; j < 4; j++) {
        x[j]     = msm[k0 + j] ? x[j] * scale     : -1e9f;
        x[4 + j] = msm[k1 + j] ? x[4 + j] * scale : -1e9f;
    }
    float m = x[0];
#pragma unroll
    for (int j = 1; j < 8; j++) m = fmaxf(m, x[j]);
#pragma unroll
    for (int o = 16; o; o >>= 1) m = fmaxf(m, __shfl_xor_sync(~0u, m, o));
    if (!lane) red[wrp] = m;
    __syncthreads();
    float M = red[0];
#pragma unroll
    for (int j = 1; j < 8; j++) M = fmaxf(M, red[j]);
    __syncthreads();

    float s = 0.f;
#pragma unroll
    for (int j = 0; j < 8; j++) { x[j] = __expf(x[j] - M); s += x[j]; }
#pragma unroll
    for (int o = 16; o; o >>= 1) s += __shfl_xor_sync(~0u, s, o);
    if (!lane) red[wrp] = s;
    __syncthreads();
    float S = red[0];
#pragma unroll
    for (int j = 1; j < 8; j++) S += red[j];
    const float inv = 1.f / S;

    ((float4*)p)[tid]       = make_float4(x[0] * inv, x[1] * inv, x[2] * inv, x[3] * inv);
    ((float4*)p)[tid + 256] = make_float4(x[4] * inv, x[5] * inv, x[6] * inv, x[7] * inv);
}

// ---------------------------------------------------------------------------
extern "C" void kernel_launch(void* const* d_in, const int* in_sizes, int n_in,
                              void* d_out, int out_size)
{
    const float* hidden = (const float*)d_in[0];
    const int*   mask   = (const int*)  d_in[1];
    const float* Wq = (const float*)d_in[2];
    const float* bq = (const float*)d_in[3];
    const float* Wk = (const float*)d_in[4];
    const float* bk = (const float*)d_in[5];
    const float* Wv = (const float*)d_in[6];
    const float* bv = (const float*)d_in[7];
    const float* Wo = (const float*)d_in[8];
    const float* bo = (const float*)d_in[9];
    float* out = (float*)d_out;

    float *qb, *kb, *vb, *vtb, *ab, *scb;
    cudaGetSymbolAddress((void**)&qb,  g_q);
    cudaGetSymbolAddress((void**)&kb,  g_k);
    cudaGetSymbolAddress((void**)&vb,  g_v);
    cudaGetSymbolAddress((void**)&vtb, g_vt);
    cudaGetSymbolAddress((void**)&ab,  g_attn);
    cudaGetSymbolAddress((void**)&scb, g_scores);

    cudaFuncSetAttribute(qkv_tc,         cudaFuncAttributeMaxDynamicSharedMemorySize, SMEM_BYTES);
    cudaFuncSetAttribute(gemm_tc<false>, cudaFuncAttributeMaxDynamicSharedMemorySize, SMEM_BYTES);
    cudaFuncSetAttribute(gemm_tc<true>,  cudaFuncAttributeMaxDynamicSharedMemorySize, SMEM_BYTES);

    // 1) Q,K,V projections (fused via grid.z)
    qkv_tc<<<dim3(DD / 128, MROWS / 128, 3), 512, SMEM_BYTES>>>(
        hidden, Wq, bq, qb, Wk, bk, kb, Wv, bv, vb);

    // 2) V transpose for PV operand
    transpose_v<<<dim3(SS / 32, HDIM / 32, BH), dim3(32, 8)>>>(vb, vtb);

    // 3) scores = Q K^T per (b,h)
    gemm_tc<false><<<dim3(SS / 128, SS / 128, BH), 512, SMEM_BYTES>>>(
        qb,  DD, (long long)SS * DD, (long long)HDIM,
        kb,  DD, (long long)SS * DD, (long long)HDIM,
        nullptr,
        scb, SS, (long long)16 * SS * SS, (long long)SS * SS, HDIM);

    // 4) masked softmax (in place, folds scale)
    softmax_kernel<<<BH * SS, 256>>>(scb, mask);

    // 5) attn = probs @ V  (B operand = V^T, K-major)
    gemm_tc<false><<<dim3(1, SS / 128, BH), 512, SMEM_BYTES>>>(
        scb, SS, (long long)16 * SS * SS, (long long)SS * SS,
        vtb, SS, (long long)16 * HDIM * SS, (long long)HDIM * SS,
        nullptr,
        ab,  DD, (long long)SS * DD, (long long)HDIM, SS);

    // 6) out = attn @ Wo^T + bo
    gemm_tc<true><<<dim3(DD / 128, MROWS / 128, 1), 512, SMEM_BYTES>>>(
        ab, DD, 0, 0, Wo, DD, 0, 0, bo, out, DD, 0, 0, DD);
}

// round 4
// speedup vs baseline: 3.0678x; 1.2829x over previous
#include <cuda_runtime.h>
#include <cuda_bf16.h>
#include <cstdint>

#define BB 2
#define SS 2048
#define DD 2048
#define HH 16
#define HDIM 128
#define MROWS (BB*SS)     // 4096
#define BH (BB*HH)        // 32

typedef __nv_bfloat16 bf16;

// ---------------------------------------------------------------------------
// Scratch (__device__ globals; cudaMalloc is forbidden)
// All operands stored as separate bf16 hi/lo planes.
// ---------------------------------------------------------------------------
__device__ bf16 g_hid_hi[(size_t)MROWS * DD], g_hid_lo[(size_t)MROWS * DD];
__device__ bf16 g_wq_hi [(size_t)DD * DD],    g_wq_lo [(size_t)DD * DD];
__device__ bf16 g_wk_hi [(size_t)DD * DD],    g_wk_lo [(size_t)DD * DD];
__device__ bf16 g_wv_hi [(size_t)DD * DD],    g_wv_lo [(size_t)DD * DD];
__device__ bf16 g_wo_hi [(size_t)DD * DD],    g_wo_lo [(size_t)DD * DD];
__device__ bf16 g_q_hi  [(size_t)MROWS * DD], g_q_lo  [(size_t)MROWS * DD];
__device__ bf16 g_k_hi  [(size_t)MROWS * DD], g_k_lo  [(size_t)MROWS * DD];
__device__ bf16 g_v_hi  [(size_t)MROWS * DD], g_v_lo  [(size_t)MROWS * DD];
__device__ bf16 g_vt_hi [(size_t)MROWS * DD], g_vt_lo [(size_t)MROWS * DD];
__device__ bf16 g_at_hi [(size_t)MROWS * DD], g_at_lo [(size_t)MROWS * DD];
__device__ bf16 g_p_hi  [(size_t)BH * SS * SS], g_p_lo[(size_t)BH * SS * SS];
__device__ float g_scores[(size_t)BH * SS * SS];        // 512 MiB

// ---------------------------------------------------------------------------
// mma.sync helpers (compute_80+, legal under plain sm_103 PTX target)
// ---------------------------------------------------------------------------
__device__ __forceinline__ uint32_t smem_u32_of(const void* p) {
    uint32_t a;
    asm("{ .reg .u64 t; cvta.to.shared.u64 t, %1; cvt.u32.u64 %0, t; }" : "=r"(a) : "l"(p));
    return a;
}
__device__ __forceinline__ void ldsm_x4(uint32_t* r, uint32_t addr) {
    asm volatile("ldmatrix.sync.aligned.m8n8.x4.shared.b16 {%0,%1,%2,%3}, [%4];"
                 : "=r"(r[0]), "=r"(r[1]), "=r"(r[2]), "=r"(r[3]) : "r"(addr));
}
__device__ __forceinline__ void mma_bf16(float* c, const uint32_t* a,
                                         uint32_t b0, uint32_t b1) {
    asm volatile(
        "mma.sync.aligned.m16n8k16.row.col.f32.bf16.bf16.f32 "
        "{%0,%1,%2,%3}, {%4,%5,%6,%7}, {%8,%9}, {%0,%1,%2,%3};"
        : "+f"(c[0]), "+f"(c[1]), "+f"(c[2]), "+f"(c[3])
        : "r"(a[0]), "r"(a[1]), "r"(a[2]), "r"(a[3]), "r"(b0), "r"(b1));
}
__device__ __forceinline__ uint32_t pack_hi2(float x, float y) {
    bf16 a = __float2bfloat16_rn(x), b = __float2bfloat16_rn(y);
    return (uint32_t)__bfloat16_as_ushort(a) | ((uint32_t)__bfloat16_as_ushort(b) << 16);
}
__device__ __forceinline__ uint32_t pack_lo2(float x, float y) {
    bf16 a = __float2bfloat16_rn(x), b = __float2bfloat16_rn(y);
    bf16 c = __float2bfloat16_rn(x - __bfloat162float(a));
    bf16 d = __float2bfloat16_rn(y - __bfloat162float(b));
    return (uint32_t)__bfloat16_as_ushort(c) | ((uint32_t)__bfloat16_as_ushort(d) << 16);
}

// ---------------------------------------------------------------------------
// Split pass: fp32 tensor -> bf16 hi/lo planes
// ---------------------------------------------------------------------------
__global__ void split_kernel(const float* __restrict__ src,
                             bf16* __restrict__ hi, bf16* __restrict__ lo, int n4)
{
    int i = blockIdx.x * blockDim.x + threadIdx.x;
    if (i >= n4) return;
    float4 v = ((const float4*)src)[i];
    uint2 h = make_uint2(pack_hi2(v.x, v.y), pack_hi2(v.z, v.w));
    uint2 l = make_uint2(pack_lo2(v.x, v.y), pack_lo2(v.z, v.w));
    ((uint2*)hi)[i] = h;
    ((uint2*)lo)[i] = l;
}

// ---------------------------------------------------------------------------
// GEMM: D[M x N] = (Ahi+Alo)[M x K] * (Bhi+Blo)[N x K]^T (+ bias)
// 3-product compensation (hh + hl + lh), fp32 mma accumulators.
// Block tile 128x128, k-tile 64. 512 threads = 16 warps (4x4), warp 32x32.
// Smem rows: 64 bf16 = 128B + 16B pad = 144B stride (conflict-free LDSM).
// ---------------------------------------------------------------------------
#define BKT 64
#define ROWB 144
#define TILEB (128*ROWB)           // 18432
#define S_STAGE (4*TILEB)          // 73728
#define SMEM_BYTES (2*S_STAGE)     // 147456

// PLANES: write hi/lo bf16 planes; else fp32. BIAS: add bias[n].
template<bool PLANES, bool BIAS>
__device__ __forceinline__ void gemm_body(
    const bf16* __restrict__ Ahi, const bf16* __restrict__ Alo, int lda,
    const bf16* __restrict__ Bhi, const bf16* __restrict__ Blo, int ldb,
    const float* __restrict__ bias,
    float* __restrict__ D, bf16* __restrict__ Dhi, bf16* __restrict__ Dlo,
    int ldd, int K)
{
    extern __shared__ __align__(1024) char smem[];
    const uint32_t sbase = smem_u32_of(smem);

    const int tid  = threadIdx.x;
    const int wid  = tid >> 5;
    const int lane = tid & 31;
    const int wm = (wid >> 2) * 32;
    const int wn = (wid & 3)  * 32;
    const int bm = blockIdx.y * 128;
    const int bn = blockIdx.x * 128;

    float acc[2][4][4];
#pragma unroll
    for (int mf = 0; mf < 2; mf++)
#pragma unroll
        for (int nf = 0; nf < 4; nf++)
#pragma unroll
            for (int e = 0; e < 4; e++) acc[mf][nf][e] = 0.f;

    const bf16* srcA[2] = { Ahi + (size_t)bm * lda, Alo + (size_t)bm * lda };
    const bf16* srcB[2] = { Bhi + (size_t)bn * ldb, Blo + (size_t)bn * ldb };

    uint4 streg[8];
    // 4096 uint4 slots per stage: tile = slot>>10 (Ahi,Alo,Bhi,Blo),
    // r = (slot>>3)&127, c8 = slot&7 (8 bf16 = 16B)
    auto gload = [&](int kt) {
#pragma unroll
        for (int i = 0; i < 8; i++) {
            int slot = tid + i * 512;
            int tile = slot >> 10;
            int r    = (slot >> 3) & 127;
            int c8   = slot & 7;
            const bf16* gp = (tile < 2)
                ? srcA[tile]     + (size_t)r * lda + kt * BKT + c8 * 8
                : srcB[tile - 2] + (size_t)r * ldb + kt * BKT + c8 * 8;
            streg[i] = *(const uint4*)gp;
        }
    };
    auto sstore = [&](int s) {
        char* st = smem + s * S_STAGE;
#pragma unroll
        for (int i = 0; i < 8; i++) {
            int slot = tid + i * 512;
            int tile = slot >> 10;
            int r    = (slot >> 3) & 127;
            int c8   = slot & 7;
            *(uint4*)(st + tile * TILEB + r * ROWB + c8 * 16) = streg[i];
        }
    };

    const int NKT = K / BKT;
    gload(0);
    sstore(0);
    __syncthreads();

    const int a_row  = lane & 15;
    const int a_colB = (lane >> 4) * 16;
    const int b_row  = (lane & 7) + ((lane & 16) ? 8 : 0);
    const int b_colB = (lane & 8) ? 16 : 0;

    for (int kt = 0; kt < NKT; kt++) {
        const int s = kt & 1;
        if (kt + 1 < NKT) gload(kt + 1);

        const uint32_t sb = sbase + s * S_STAGE;
#pragma unroll
        for (int ks = 0; ks < 4; ks++) {
            uint32_t ah[2][4], al[2][4], bh[2][4], bl[2][4];
            const int kB = ks * 32;   // 16 bf16 = 32 bytes
#pragma unroll
            for (int mf = 0; mf < 2; mf++) {
                uint32_t ad = sb + (wm + mf * 16 + a_row) * ROWB + a_colB + kB;
                ldsm_x4(ah[mf], ad);
                ldsm_x4(al[mf], ad + TILEB);
            }
#pragma unroll
            for (int np = 0; np < 2; np++) {
                uint32_t bd = sb + 2 * TILEB + (wn + np * 16 + b_row) * ROWB + b_colB + kB;
                ldsm_x4(bh[np], bd);
                ldsm_x4(bl[np], bd + TILEB);
            }
#pragma unroll
            for (int mf = 0; mf < 2; mf++)
#pragma unroll
                for (int np = 0; np < 2; np++)
#pragma unroll
                    for (int h = 0; h < 2; h++) {
                        int nf = np * 2 + h;
                        mma_bf16(acc[mf][nf], ah[mf], bh[np][2*h], bh[np][2*h+1]);
                        mma_bf16(acc[mf][nf], ah[mf], bl[np][2*h], bl[np][2*h+1]);
                        mma_bf16(acc[mf][nf], al[mf], bh[np][2*h], bh[np][2*h+1]);
                    }
        }
        if (kt + 1 < NKT) sstore((kt + 1) & 1);
        __syncthreads();
    }

    // Epilogue
    const int er = lane >> 2;
    const int ec = (lane & 3) * 2;
#pragma unroll
    for (int mf = 0; mf < 2; mf++) {
#pragma unroll
        for (int nf = 0; nf < 4; nf++) {
            int gr = bm + wm + mf * 16 + er;
            int gc = bn + wn + nf * 8 + ec;
            float b0 = 0.f, b1 = 0.f;
            if (BIAS) { b0 = bias[gc]; b1 = bias[gc + 1]; }
            float x0 = acc[mf][nf][0] + b0, x1 = acc[mf][nf][1] + b1;
            float x2 = acc[mf][nf][2] + b0, x3 = acc[mf][nf][3] + b1;
            if (PLANES) {
                size_t o0 = (size_t)gr * ldd + gc;
                size_t o1 = (size_t)(gr + 8) * ldd + gc;
                *(uint32_t*)(Dhi + o0) = pack_hi2(x0, x1);
                *(uint32_t*)(Dlo + o0) = pack_lo2(x0, x1);
                *(uint32_t*)(Dhi + o1) = pack_hi2(x2, x3);
                *(uint32_t*)(Dlo + o1) = pack_lo2(x2, x3);
            } else {
                *(float2*)(D + (size_t)gr * ldd + gc)       = make_float2(x0, x1);
                *(float2*)(D + (size_t)(gr + 8) * ldd + gc) = make_float2(x2, x3);
            }
        }
    }
}

// Generic z-batched wrapper: per-z offsets = (z/16)*zb + (z%16)*zh
template<bool PLANES, bool BIAS>
__global__ __launch_bounds__(512, 1) void gemm_tc(
    const bf16* Ahi, const bf16* Alo, int lda, long long azb, long long azh,
    const bf16* Bhi, const bf16* Blo, int ldb, long long bzb, long long bzh,
    const float* bias,
    float* D, bf16* Dhi, bf16* Dlo, int ldd, long long dzb, long long dzh, int K)
{
    const long long zb = blockIdx.z >> 4, zh = blockIdx.z & 15;
    const long long ao = zb * azb + zh * azh;
    const long long bo = zb * bzb + zh * bzh;
    const long long dzo = zb * dzb + zh * dzh;
    gemm_body<PLANES, BIAS>(Ahi + ao, Alo + ao, lda,
                            Bhi + bo, Blo + bo, ldb, bias,
                            PLANES ? nullptr : D + dzo,
                            PLANES ? Dhi + dzo : nullptr,
                            PLANES ? Dlo + dzo : nullptr, ldd, K);
}

// Fused QKV: z in {0,1,2} picks projection; outputs hi/lo planes
__global__ __launch_bounds__(512, 1) void qkv_tc(
    const bf16* hhi, const bf16* hlo,
    const bf16* wqh, const bf16* wql, const float* bq, bf16* qhi, bf16* qlo,
    const bf16* wkh, const bf16* wkl, const float* bk, bf16* khi, bf16* klo,
    const bf16* wvh, const bf16* wvl, const float* bv, bf16* vhi, bf16* vlo)
{
    const bf16 *Wh, *Wl; const float* b; bf16 *Dh, *Dl;
    if (blockIdx.z == 0)      { Wh = wqh; Wl = wql; b = bq; Dh = qhi; Dl = qlo; }
    else if (blockIdx.z == 1) { Wh = wkh; Wl = wkl; b = bk; Dh = khi; Dl = klo; }
    else                      { Wh = wvh; Wl = wvl; b = bv; Dh = vhi; Dl = vlo; }
    gemm_body<true, true>(hhi, hlo, DD, Wh, Wl, DD, b, nullptr, Dh, Dl, DD, DD);
}

// ---------------------------------------------------------------------------
// V transpose (bf16 plane): v[(b,s), h*128+d] -> vt[(bh*128+d), s]
// ---------------------------------------------------------------------------
__global__ void transpose_plane(const bf16* __restrict__ v, bf16* __restrict__ vt)
{
    __shared__ unsigned short t[32][36];
    const int bh = blockIdx.z;
    const int b = bh >> 4, h = bh & 15;
    const int s0 = blockIdx.x * 32, d0 = blockIdx.y * 32;
    const int tx = threadIdx.x, ty = threadIdx.y;
    const unsigned short* vs = (const unsigned short*)v;
    unsigned short* vd = (unsigned short*)vt;
#pragma unroll
    for (int i = 0; i < 32; i += 8)
        t[ty + i][tx] = vs[(size_t)(b * SS + s0 + ty + i) * DD + h * HDIM + d0 + tx];
    __syncthreads();
#pragma unroll
    for (int i = 0; i < 32; i += 8)
        vd[(size_t)(bh * HDIM + d0 + ty + i) * SS + s0 + tx] = t[tx][ty + i];
}

// ---------------------------------------------------------------------------
// Masked softmax: reads fp32 scores, writes P as bf16 hi/lo planes.
// Folds 1/sqrt(HD).
// ---------------------------------------------------------------------------
__global__ __launch_bounds__(256) void softmax_kernel(
    const float* __restrict__ sc, const int* __restrict__ mask,
    bf16* __restrict__ phi, bf16* __restrict__ plo)
{
    __shared__ float red[8];
    __shared__ int msm[SS];
    const int row = blockIdx.x;
    const int b = row >> 15;
    const float* p = sc + (size_t)row * SS;
    const int* mk = mask + (size_t)b * SS;
    const int tid = threadIdx.x;
    const int lane = tid & 31, wrp = tid >> 5;
    const float scale = 0.08838834764831845f;

    for (int i = tid; i < SS / 4; i += 256) ((int4*)msm)[i] = ((const int4*)mk)[i];
    __syncthreads();

    float4 v0 = ((const float4*)p)[tid];
    float4 v1 = ((const float4*)p)[tid + 256];
    float x[8] = {v0.x, v0.y, v0.z, v0.w, v1.x, v1.y, v1.z, v1.w};
    const int k0 = tid * 4, k1 = (tid + 256) * 4;
#pragma unroll
    for (int j = 0; j < 4; j++) {
        x[j]     = msm[k0 + j] ? x[j] * scale     : -1e9f;
        x[4 + j] = msm[k1 + j] ? x[4 + j] * scale : -1e9f;
    }
    float m = x[0];
#pragma unroll
    for (int j = 1; j < 8; j++) m = fmaxf(m, x[j]);
#pragma unroll
    for (int o = 16; o; o >>= 1) m = fmaxf(m, __shfl_xor_sync(~0u, m, o));
    if (!lane) red[wrp] = m;
    __syncthreads();
    float M = red[0];
#pragma unroll
    for (int j = 1; j < 8; j++) M = fmaxf(M, red[j]);
    __syncthreads();

    float s = 0.f;
#pragma unroll
    for (int j = 0; j < 8; j++) { x[j] = __expf(x[j] - M); s += x[j]; }
#pragma unroll
    for (int o = 16; o; o >>= 1) s += __shfl_xor_sync(~0u, s, o);
    if (!lane) red[wrp] = s;
    __syncthreads();
    float S = red[0];
#pragma unroll
    for (int j = 1; j < 8; j++) S += red[j];
    const float inv = 1.f / S;
#pragma unroll
    for (int j = 0; j < 8; j++) x[j] *= inv;

    const size_t base = (size_t)row * SS;
    *(uint2*)(phi + base + k0) = make_uint2(pack_hi2(x[0], x[1]), pack_hi2(x[2], x[3]));
    *(uint2*)(plo + base + k0) = make_uint2(pack_lo2(x[0], x[1]), pack_lo2(x[2], x[3]));
    *(uint2*)(phi + base + k1) = make_uint2(pack_hi2(x[4], x[5]), pack_hi2(x[6], x[7]));
    *(uint2*)(plo + base + k1) = make_uint2(pack_lo2(x[4], x[5]), pack_lo2(x[6], x[7]));
}

// ---------------------------------------------------------------------------
extern "C" void kernel_launch(void* const* d_in, const int* in_sizes, int n_in,
                              void* d_out, int out_size)
{
    const float* hidden = (const float*)d_in[0];
    const int*   mask   = (const int*)  d_in[1];
    const float* Wq = (const float*)d_in[2];
    const float* bq = (const float*)d_in[3];
    const float* Wk = (const float*)d_in[4];
    const float* bk = (const float*)d_in[5];
    const float* Wv = (const float*)d_in[6];
    const float* bv = (const float*)d_in[7];
    const float* Wo = (const float*)d_in[8];
    const float* bo = (const float*)d_in[9];
    float* out = (float*)d_out;

    bf16 *hh,*hl,*wqh,*wql,*wkh,*wkl,*wvh,*wvl,*woh,*wol;
    bf16 *qh,*ql,*kh,*kl,*vh,*vl,*vth,*vtl,*ath,*atl,*ph,*pl;
    float *scb;
    cudaGetSymbolAddress((void**)&hh,  g_hid_hi); cudaGetSymbolAddress((void**)&hl,  g_hid_lo);
    cudaGetSymbolAddress((void**)&wqh, g_wq_hi);  cudaGetSymbolAddress((void**)&wql, g_wq_lo);
    cudaGetSymbolAddress((void**)&wkh, g_wk_hi);  cudaGetSymbolAddress((void**)&wkl, g_wk_lo);
    cudaGetSymbolAddress((void**)&wvh, g_wv_hi);  cudaGetSymbolAddress((void**)&wvl, g_wv_lo);
    cudaGetSymbolAddress((void**)&woh, g_wo_hi);  cudaGetSymbolAddress((void**)&wol, g_wo_lo);
    cudaGetSymbolAddress((void**)&qh,  g_q_hi);   cudaGetSymbolAddress((void**)&ql,  g_q_lo);
    cudaGetSymbolAddress((void**)&kh,  g_k_hi);   cudaGetSymbolAddress((void**)&kl,  g_k_lo);
    cudaGetSymbolAddress((void**)&vh,  g_v_hi);   cudaGetSymbolAddress((void**)&vl,  g_v_lo);
    cudaGetSymbolAddress((void**)&vth, g_vt_hi);  cudaGetSymbolAddress((void**)&vtl, g_vt_lo);
    cudaGetSymbolAddress((void**)&ath, g_at_hi);  cudaGetSymbolAddress((void**)&atl, g_at_lo);
    cudaGetSymbolAddress((void**)&ph,  g_p_hi);   cudaGetSymbolAddress((void**)&pl,  g_p_lo);
    cudaGetSymbolAddress((void**)&scb, g_scores);

    cudaFuncSetAttribute(qkv_tc,                cudaFuncAttributeMaxDynamicSharedMemorySize, SMEM_BYTES);
    cudaFuncSetAttribute(gemm_tc<false,false>,  cudaFuncAttributeMaxDynamicSharedMemorySize, SMEM_BYTES);
    cudaFuncSetAttribute(gemm_tc<false,true>,   cudaFuncAttributeMaxDynamicSharedMemorySize, SMEM_BYTES);
    cudaFuncSetAttribute(gemm_tc<true,false>,   cudaFuncAttributeMaxDynamicSharedMemorySize, SMEM_BYTES);

    // 0) split fp32 inputs into bf16 hi/lo planes
    {
        const int T = 256;
        int nh4 = (MROWS * DD) / 4, nw4 = (DD * DD) / 4;
        split_kernel<<<(nh4 + T - 1) / T, T>>>(hidden, hh, hl, nh4);
        split_kernel<<<(nw4 + T - 1) / T, T>>>(Wq, wqh, wql, nw4);
        split_kernel<<<(nw4 + T - 1) / T, T>>>(Wk, wkh, wkl, nw4);
        split_kernel<<<(nw4 + T - 1) / T, T>>>(Wv, wvh, wvl, nw4);
        split_kernel<<<(nw4 + T - 1) / T, T>>>(Wo, woh, wol, nw4);
    }

    // 1) Q,K,V projections (fused via grid.z) -> planes
    qkv_tc<<<dim3(DD / 128, MROWS / 128, 3), 512, SMEM_BYTES>>>(
        hh, hl, wqh, wql, bq, qh, ql, wkh, wkl, bk, kh, kl, wvh, wvl, bv, vh, vl);

    // 2) V transpose (both planes)
    transpose_plane<<<dim3(SS / 32, HDIM / 32, BH), dim3(32, 8)>>>(vh, vth);
    transpose_plane<<<dim3(SS / 32, HDIM / 32, BH), dim3(32, 8)>>>(vl, vtl);

    // 3) scores = Q K^T per (b,h)  -> fp32
    gemm_tc<false,false><<<dim3(SS / 128, SS / 128, BH), 512, SMEM_BYTES>>>(
        qh, ql, DD, (long long)SS * DD, (long long)HDIM,
        kh, kl, DD, (long long)SS * DD, (long long)HDIM,
        nullptr,
        scb, nullptr, nullptr, SS, (long long)16 * SS * SS, (long long)SS * SS, HDIM);

    // 4) masked softmax -> P planes
    softmax_kernel<<<BH * SS, 256>>>(scb, mask, ph, pl);

    // 5) attn = P @ V  (B operand = V^T planes) -> attn planes
    gemm_tc<true,false><<<dim3(HDIM / 128, SS / 128, BH), 512, SMEM_BYTES>>>(
        ph, pl, SS, (long long)16 * SS * SS, (long long)SS * SS,
        vth, vtl, SS, (long long)16 * HDIM * SS, (long long)HDIM * SS,
        nullptr,
        nullptr, ath, atl, DD, (long long)SS * DD, (long long)HDIM, SS);

    // 6) out = attn @ Wo^T + bo -> fp32
    gemm_tc<false,true><<<dim3(DD / 128, MROWS / 128, 1), 512, SMEM_BYTES>>>(
        ath, atl, DD, 0, 0, woh, wol, DD, 0, 0, bo,
        out, nullptr, nullptr, DD, 0, 0, DD);
}

// round 5
// speedup vs baseline: 3.3799x; 1.1017x over previous
#include <cuda_runtime.h>
#include <cuda_bf16.h>
#include <cuda_fp16.h>
#include <cstdint>

#define BB 2
#define SS 2048
#define DD 2048
#define HH 16
#define HDIM 128
#define MROWS (BB*SS)     // 4096
#define BH (BB*HH)        // 32

typedef __nv_bfloat16 bf16;
typedef __half fp16;
typedef long long ll;

// ---------------------------------------------------------------------------
// Scratch (__device__ globals; cudaMalloc is forbidden)
// ---------------------------------------------------------------------------
__device__ bf16 g_hid_hi[(size_t)MROWS * DD], g_hid_lo[(size_t)MROWS * DD];
__device__ bf16 g_wq_hi [(size_t)DD * DD],    g_wq_lo [(size_t)DD * DD];
__device__ bf16 g_wk_hi [(size_t)DD * DD],    g_wk_lo [(size_t)DD * DD];
__device__ bf16 g_wv_hi [(size_t)DD * DD],    g_wv_lo [(size_t)DD * DD];
__device__ bf16 g_wo_hi [(size_t)DD * DD],    g_wo_lo [(size_t)DD * DD];
__device__ bf16 g_q_hi  [(size_t)MROWS * DD], g_q_lo  [(size_t)MROWS * DD];
__device__ bf16 g_k_hi  [(size_t)MROWS * DD], g_k_lo  [(size_t)MROWS * DD];
__device__ fp16 g_v_h16 [(size_t)MROWS * DD];
__device__ fp16 g_vt_h16[(size_t)MROWS * DD];           // [bh][128][2048]
__device__ bf16 g_at_hi [(size_t)MROWS * DD], g_at_lo [(size_t)MROWS * DD];
__device__ fp16 g_p_h16 [(size_t)BH * SS * SS];         // 256 MiB
__device__ float g_scores[(size_t)BH * SS * SS];        // 512 MiB

// ---------------------------------------------------------------------------
// mma.sync helpers (compute_80+, legal under plain sm_103 PTX target)
// ---------------------------------------------------------------------------
__device__ __forceinline__ uint32_t smem_u32_of(const void* p) {
    uint32_t a;
    asm("{ .reg .u64 t; cvta.to.shared.u64 t, %1; cvt.u32.u64 %0, t; }" : "=r"(a) : "l"(p));
    return a;
}
__device__ __forceinline__ void ldsm_x4(uint32_t* r, uint32_t addr) {
    asm volatile("ldmatrix.sync.aligned.m8n8.x4.shared.b16 {%0,%1,%2,%3}, [%4];"
                 : "=r"(r[0]), "=r"(r[1]), "=r"(r[2]), "=r"(r[3]) : "r"(addr));
}
__device__ __forceinline__ void mma_bf16(float* c, const uint32_t* a,
                                         uint32_t b0, uint32_t b1) {
    asm volatile(
        "mma.sync.aligned.m16n8k16.row.col.f32.bf16.bf16.f32 "
        "{%0,%1,%2,%3}, {%4,%5,%6,%7}, {%8,%9}, {%0,%1,%2,%3};"
        : "+f"(c[0]), "+f"(c[1]), "+f"(c[2]), "+f"(c[3])
        : "r"(a[0]), "r"(a[1]), "r"(a[2]), "r"(a[3]), "r"(b0), "r"(b1));
}
__device__ __forceinline__ void mma_fp16(float* c, const uint32_t* a,
                                         uint32_t b0, uint32_t b1) {
    asm volatile(
        "mma.sync.aligned.m16n8k16.row.col.f32.f16.f16.f32 "
        "{%0,%1,%2,%3}, {%4,%5,%6,%7}, {%8,%9}, {%0,%1,%2,%3};"
        : "+f"(c[0]), "+f"(c[1]), "+f"(c[2]), "+f"(c[3])
        : "r"(a[0]), "r"(a[1]), "r"(a[2]), "r"(a[3]), "r"(b0), "r"(b1));
}
__device__ __forceinline__ uint32_t pack_hi2(float x, float y) {
    bf16 a = __float2bfloat16_rn(x), b = __float2bfloat16_rn(y);
    return (uint32_t)__bfloat16_as_ushort(a) | ((uint32_t)__bfloat16_as_ushort(b) << 16);
}
__device__ __forceinline__ uint32_t pack_lo2(float x, float y) {
    bf16 a = __float2bfloat16_rn(x), b = __float2bfloat16_rn(y);
    bf16 c = __float2bfloat16_rn(x - __bfloat162float(a));
    bf16 d = __float2bfloat16_rn(y - __bfloat162float(b));
    return (uint32_t)__bfloat16_as_ushort(c) | ((uint32_t)__bfloat16_as_ushort(d) << 16);
}
__device__ __forceinline__ uint32_t pack_f16_2(float x, float y) {
    __half2 h = __floats2half2_rn(x, y);
    return *(uint32_t*)&h;
}

// ---------------------------------------------------------------------------
// Split pass: fp32 tensor -> bf16 hi/lo planes
// ---------------------------------------------------------------------------
__global__ void split_kernel(const float* __restrict__ src,
                             bf16* __restrict__ hi, bf16* __restrict__ lo, int n4)
{
    int i = blockIdx.x * blockDim.x + threadIdx.x;
    if (i >= n4) return;
    float4 v = ((const float4*)src)[i];
    ((uint2*)hi)[i] = make_uint2(pack_hi2(v.x, v.y), pack_hi2(v.z, v.w));
    ((uint2*)lo)[i] = make_uint2(pack_lo2(v.x, v.y), pack_lo2(v.z, v.w));
}

// ---------------------------------------------------------------------------
// Shared GEMM geometry: block tile 128x128, k-tile 64, 512 threads = 16 warps
// (4x4), warp tile 32x32. Smem rows 64 elems * 2B = 128B + 16B pad = 144B.
// ---------------------------------------------------------------------------
#define BKT 64
#define ROWB 144
#define TILEB (128*ROWB)           // 18432
#define S3_STAGE (4*TILEB)         // 73728 (Ahi,Alo,Bhi,Blo)
#define SMEM3 (2*S3_STAGE)         // 147456
#define S1_STAGE (2*TILEB)         // 36864 (A,B)
#define SMEM1 (2*S1_STAGE)         // 73728

// outmode: 0 = fp32 D, 1 = bf16 hi/lo planes, 2 = fp16 plane. bias optional.
__device__ __forceinline__ void epilogue_store(
    int outmode, const float* bias,
    float* D, bf16* Dhi, bf16* Dlo, fp16* Dh16, int ldd,
    int bm, int bn, int wm, int wn, int lane, float acc[2][4][4])
{
    const int er = lane >> 2;
    const int ec = (lane & 3) * 2;
#pragma unroll
    for (int mf = 0; mf < 2; mf++) {
#pragma unroll
        for (int nf = 0; nf < 4; nf++) {
            int gr = bm + wm + mf * 16 + er;
            int gc = bn + wn + nf * 8 + ec;
            float b0 = 0.f, b1 = 0.f;
            if (bias) { b0 = bias[gc]; b1 = bias[gc + 1]; }
            float x0 = acc[mf][nf][0] + b0, x1 = acc[mf][nf][1] + b1;
            float x2 = acc[mf][nf][2] + b0, x3 = acc[mf][nf][3] + b1;
            size_t o0 = (size_t)gr * ldd + gc;
            size_t o1 = (size_t)(gr + 8) * ldd + gc;
            if (outmode == 0) {
                *(float2*)(D + o0) = make_float2(x0, x1);
                *(float2*)(D + o1) = make_float2(x2, x3);
            } else if (outmode == 1) {
                *(uint32_t*)(Dhi + o0) = pack_hi2(x0, x1);
                *(uint32_t*)(Dlo + o0) = pack_lo2(x0, x1);
                *(uint32_t*)(Dhi + o1) = pack_hi2(x2, x3);
                *(uint32_t*)(Dlo + o1) = pack_lo2(x2, x3);
            } else {
                *(uint32_t*)(Dh16 + o0) = pack_f16_2(x0, x1);
                *(uint32_t*)(Dh16 + o1) = pack_f16_2(x2, x3);
            }
        }
    }
}

// ---------------------------------------------------------------------------
// bf16 3-product GEMM body: D = (Ahi+Alo)(Bhi+Blo)^T (+bias)
// ---------------------------------------------------------------------------
__device__ __forceinline__ void gemm_bf3_body(
    const bf16* __restrict__ Ahi, const bf16* __restrict__ Alo, int lda,
    const bf16* __restrict__ Bhi, const bf16* __restrict__ Blo, int ldb,
    const float* __restrict__ bias,
    float* __restrict__ D, bf16* __restrict__ Dhi, bf16* __restrict__ Dlo,
    fp16* __restrict__ Dh16, int ldd, int K, int outmode)
{
    extern __shared__ __align__(1024) char smem[];
    const uint32_t sbase = smem_u32_of(smem);

    const int tid  = threadIdx.x;
    const int wid  = tid >> 5;
    const int lane = tid & 31;
    const int wm = (wid >> 2) * 32;
    const int wn = (wid & 3)  * 32;
    const int bm = blockIdx.y * 128;
    const int bn = blockIdx.x * 128;

    float acc[2][4][4];
#pragma unroll
    for (int mf = 0; mf < 2; mf++)
#pragma unroll
        for (int nf = 0; nf < 4; nf++)
#pragma unroll
            for (int e = 0; e < 4; e++) acc[mf][nf][e] = 0.f;

    const bf16* srcA[2] = { Ahi + (size_t)bm * lda, Alo + (size_t)bm * lda };
    const bf16* srcB[2] = { Bhi + (size_t)bn * ldb, Blo + (size_t)bn * ldb };

    uint4 streg[8];
    auto gload = [&](int kt) {
#pragma unroll
        for (int i = 0; i < 8; i++) {
            int slot = tid + i * 512;
            int tile = slot >> 10;
            int r    = (slot >> 3) & 127;
            int c8   = slot & 7;
            const bf16* gp = (tile < 2)
                ? srcA[tile]     + (size_t)r * lda + kt * BKT + c8 * 8
                : srcB[tile - 2] + (size_t)r * ldb + kt * BKT + c8 * 8;
            streg[i] = *(const uint4*)gp;
        }
    };
    auto sstore = [&](int s) {
        char* st = smem + s * S3_STAGE;
#pragma unroll
        for (int i = 0; i < 8; i++) {
            int slot = tid + i * 512;
            int tile = slot >> 10;
            int r    = (slot >> 3) & 127;
            int c8   = slot & 7;
            *(uint4*)(st + tile * TILEB + r * ROWB + c8 * 16) = streg[i];
        }
    };

    const int NKT = K / BKT;
    gload(0);
    sstore(0);
    __syncthreads();

    const int a_row  = lane & 15;
    const int a_colB = (lane >> 4) * 16;
    const int b_row  = (lane & 7) + ((lane & 16) ? 8 : 0);
    const int b_colB = (lane & 8) ? 16 : 0;

    for (int kt = 0; kt < NKT; kt++) {
        const int s = kt & 1;
        if (kt + 1 < NKT) gload(kt + 1);

        const uint32_t sb = sbase + s * S3_STAGE;
#pragma unroll
        for (int ks = 0; ks < 4; ks++) {
            uint32_t ah[2][4], al[2][4], bh[2][4], bl[2][4];
            const int kB = ks * 32;
#pragma unroll
            for (int mf = 0; mf < 2; mf++) {
                uint32_t ad = sb + (wm + mf * 16 + a_row) * ROWB + a_colB + kB;
                ldsm_x4(ah[mf], ad);
                ldsm_x4(al[mf], ad + TILEB);
            }
#pragma unroll
            for (int np = 0; np < 2; np++) {
                uint32_t bd = sb + 2 * TILEB + (wn + np * 16 + b_row) * ROWB + b_colB + kB;
                ldsm_x4(bh[np], bd);
                ldsm_x4(bl[np], bd + TILEB);
            }
#pragma unroll
            for (int mf = 0; mf < 2; mf++)
#pragma unroll
                for (int np = 0; np < 2; np++)
#pragma unroll
                    for (int h = 0; h < 2; h++) {
                        int nf = np * 2 + h;
                        mma_bf16(acc[mf][nf], ah[mf], bh[np][2*h], bh[np][2*h+1]);
                        mma_bf16(acc[mf][nf], ah[mf], bl[np][2*h], bl[np][2*h+1]);
                        mma_bf16(acc[mf][nf], al[mf], bh[np][2*h], bh[np][2*h+1]);
                    }
        }
        if (kt + 1 < NKT) sstore((kt + 1) & 1);
        __syncthreads();
    }

    epilogue_store(outmode, bias, D, Dhi, Dlo, Dh16, ldd, bm, bn, wm, wn, lane, acc);
}

// ---------------------------------------------------------------------------
// fp16 1-product GEMM body: D = A B^T, writes bf16 hi/lo planes
// ---------------------------------------------------------------------------
__device__ __forceinline__ void gemm_fp1_body(
    const fp16* __restrict__ A, int lda,
    const fp16* __restrict__ Bw, int ldb,
    bf16* __restrict__ Dhi, bf16* __restrict__ Dlo, int ldd, int K)
{
    extern __shared__ __align__(1024) char smem[];
    const uint32_t sbase = smem_u32_of(smem);

    const int tid  = threadIdx.x;
    const int wid  = tid >> 5;
    const int lane = tid & 31;
    const int wm = (wid >> 2) * 32;
    const int wn = (wid & 3)  * 32;
    const int bm = blockIdx.y * 128;
    const int bn = blockIdx.x * 128;

    float acc[2][4][4];
#pragma unroll
    for (int mf = 0; mf < 2; mf++)
#pragma unroll
        for (int nf = 0; nf < 4; nf++)
#pragma unroll
            for (int e = 0; e < 4; e++) acc[mf][nf][e] = 0.f;

    const fp16* srcA = A  + (size_t)bm * lda;
    const fp16* srcB = Bw + (size_t)bn * ldb;

    uint4 streg[4];
    auto gload = [&](int kt) {
#pragma unroll
        for (int i = 0; i < 4; i++) {
            int slot = tid + i * 512;          // 0..2047
            int tile = slot >> 10;             // 0=A, 1=B
            int r    = (slot >> 3) & 127;
            int c8   = slot & 7;
            const fp16* gp = (tile == 0)
                ? srcA + (size_t)r * lda + kt * BKT + c8 * 8
                : srcB + (size_t)r * ldb + kt * BKT + c8 * 8;
            streg[i] = *(const uint4*)gp;
        }
    };
    auto sstore = [&](int s) {
        char* st = smem + s * S1_STAGE;
#pragma unroll
        for (int i = 0; i < 4; i++) {
            int slot = tid + i * 512;
            int tile = slot >> 10;
            int r    = (slot >> 3) & 127;
            int c8   = slot & 7;
            *(uint4*)(st + tile * TILEB + r * ROWB + c8 * 16) = streg[i];
        }
    };

    const int NKT = K / BKT;
    gload(0);
    sstore(0);
    __syncthreads();

    const int a_row  = lane & 15;
    const int a_colB = (lane >> 4) * 16;
    const int b_row  = (lane & 7) + ((lane & 16) ? 8 : 0);
    const int b_colB = (lane & 8) ? 16 : 0;

    for (int kt = 0; kt < NKT; kt++) {
        const int s = kt & 1;
        if (kt + 1 < NKT) gload(kt + 1);

        const uint32_t sb = sbase + s * S1_STAGE;
#pragma unroll
        for (int ks = 0; ks < 4; ks++) {
            uint32_t ah[2][4], bh[2][4];
            const int kB = ks * 32;
#pragma unroll
            for (int mf = 0; mf < 2; mf++)
                ldsm_x4(ah[mf], sb + (wm + mf * 16 + a_row) * ROWB + a_colB + kB);
#pragma unroll
            for (int np = 0; np < 2; np++)
                ldsm_x4(bh[np], sb + TILEB + (wn + np * 16 + b_row) * ROWB + b_colB + kB);
#pragma unroll
            for (int mf = 0; mf < 2; mf++)
#pragma unroll
                for (int np = 0; np < 2; np++)
#pragma unroll
                    for (int h = 0; h < 2; h++)
                        mma_fp16(acc[mf][np * 2 + h], ah[mf], bh[np][2*h], bh[np][2*h+1]);
        }
        if (kt + 1 < NKT) sstore((kt + 1) & 1);
        __syncthreads();
    }

    epilogue_store(1, nullptr, nullptr, Dhi, Dlo, nullptr, ldd, bm, bn, wm, wn, lane, acc);
}

// ---------------------------------------------------------------------------
// Kernel wrappers
// ---------------------------------------------------------------------------
__global__ __launch_bounds__(512, 1) void gemm_bf3(
    const bf16* Ahi, const bf16* Alo, int lda, ll azb, ll azh,
    const bf16* Bhi, const bf16* Blo, int ldb, ll bzb, ll bzh,
    const float* bias,
    float* D, int ldd, ll dzb, ll dzh, int K)
{
    const ll zb = blockIdx.z >> 4, zh = blockIdx.z & 15;
    const ll ao = zb * azb + zh * azh;
    const ll bo = zb * bzb + zh * bzh;
    const ll dzo = zb * dzb + zh * dzh;
    gemm_bf3_body(Ahi + ao, Alo + ao, lda, Bhi + bo, Blo + bo, ldb, bias,
                  D + dzo, nullptr, nullptr, nullptr, ldd, K, 0);
}

__global__ __launch_bounds__(512, 1) void gemm_pv(
    const fp16* A, int lda, ll azb, ll azh,
    const fp16* Bw, int ldb, ll bzb, ll bzh,
    bf16* Dhi, bf16* Dlo, int ldd, ll dzb, ll dzh, int K)
{
    const ll zb = blockIdx.z >> 4, zh = blockIdx.z & 15;
    const ll ao = zb * azb + zh * azh;
    const ll bo = zb * bzb + zh * bzh;
    const ll dzo = zb * dzb + zh * dzh;
    gemm_fp1_body(A + ao, lda, Bw + bo, ldb, Dhi + dzo, Dlo + dzo, ldd, K);
}

// Fused QKV: z in {0,1}: bf16 planes out (q,k); z==2: fp16 plane out (v)
__global__ __launch_bounds__(512, 1) void qkv_tc(
    const bf16* hhi, const bf16* hlo,
    const bf16* wqh, const bf16* wql, const float* bq, bf16* qhi, bf16* qlo,
    const bf16* wkh, const bf16* wkl, const float* bk, bf16* khi, bf16* klo,
    const bf16* wvh, const bf16* wvl, const float* bv, fp16* vh16)
{
    if (blockIdx.z == 0)
        gemm_bf3_body(hhi, hlo, DD, wqh, wql, DD, bq, nullptr, qhi, qlo, nullptr, DD, DD, 1);
    else if (blockIdx.z == 1)
        gemm_bf3_body(hhi, hlo, DD, wkh, wkl, DD, bk, nullptr, khi, klo, nullptr, DD, DD, 1);
    else
        gemm_bf3_body(hhi, hlo, DD, wvh, wvl, DD, bv, nullptr, nullptr, nullptr, vh16, DD, DD, 2);
}

// ---------------------------------------------------------------------------
// Transpose of a 16-bit plane: v[(b,s), h*128+d] -> vt[(bh*128+d), s]
// ---------------------------------------------------------------------------
__global__ void transpose_plane(const unsigned short* __restrict__ vs,
                                unsigned short* __restrict__ vd)
{
    __shared__ unsigned short t[32][36];
    const int bh = blockIdx.z;
    const int b = bh >> 4, h = bh & 15;
    const int s0 = blockIdx.x * 32, d0 = blockIdx.y * 32;
    const int tx = threadIdx.x, ty = threadIdx.y;
#pragma unroll
    for (int i = 0; i < 32; i += 8)
        t[ty + i][tx] = vs[(size_t)(b * SS + s0 + ty + i) * DD + h * HDIM + d0 + tx];
    __syncthreads();
#pragma unroll
    for (int i = 0; i < 32; i += 8)
        vd[(size_t)(bh * HDIM + d0 + ty + i) * SS + s0 + tx] = t[tx][ty + i];
}

// ---------------------------------------------------------------------------
// Masked softmax: reads fp32 scores, writes P as a single fp16 plane.
// Folds 1/sqrt(HD).
// ---------------------------------------------------------------------------
__global__ __launch_bounds__(256) void softmax_kernel(
    const float* __restrict__ sc, const int* __restrict__ mask,
    fp16* __restrict__ ph)
{
    __shared__ float red[8];
    __shared__ int msm[SS];
    const int row = blockIdx.x;
    const int b = row >> 15;
    const float* p = sc + (size_t)row * SS;
    const int* mk = mask + (size_t)b * SS;
    const int tid = threadIdx.x;
    const int lane = tid & 31, wrp = tid >> 5;
    const float scale = 0.08838834764831845f;

    for (int i = tid; i < SS / 4; i += 256) ((int4*)msm)[i] = ((const int4*)mk)[i];
    __syncthreads();

    float4 v0 = ((const float4*)p)[tid];
    float4 v1 = ((const float4*)p)[tid + 256];
    float x[8] = {v0.x, v0.y, v0.z, v0.w, v1.x, v1.y, v1.z, v1.w};
    const int k0 = tid * 4, k1 = (tid + 256) * 4;
#pragma unroll
    for (int j = 0; j < 4; j++) {
        x[j]     = msm[k0 + j] ? x[j] * scale     : -1e9f;
        x[4 + j] = msm[k1 + j] ? x[4 + j] * scale : -1e9f;
    }
    float m = x[0];
#pragma unroll
    for (int j = 1; j < 8; j++) m = fmaxf(m, x[j]);
#pragma unroll
    for (int o = 16; o; o >>= 1) m = fmaxf(m, __shfl_xor_sync(~0u, m, o));
    if (!lane) red[wrp] = m;
    __syncthreads();
    float M = red[0];
#pragma unroll
    for (int j = 1; j < 8; j++) M = fmaxf(M, red[j]);
    __syncthreads();

    float s = 0.f;
#pragma unroll
    for (int j = 0; j < 8; j++) { x[j] = __expf(x[j] - M); s += x[j]; }
#pragma unroll
    for (int o = 16; o; o >>= 1) s += __shfl_xor_sync(~0u, s, o);
    if (!lane) red[wrp] = s;
    __syncthreads();
    float S = red[0];
#pragma unroll
    for (int j = 1; j < 8; j++) S += red[j];
    const float inv = 1.f / S;
#pragma unroll
    for (int j = 0; j < 8; j++) x[j] *= inv;

    const size_t base = (size_t)row * SS;
    *(uint2*)(ph + base + k0) = make_uint2(pack_f16_2(x[0], x[1]), pack_f16_2(x[2], x[3]));
    *(uint2*)(ph + base + k1) = make_uint2(pack_f16_2(x[4], x[5]), pack_f16_2(x[6], x[7]));
}

// ---------------------------------------------------------------------------
extern "C" void kernel_launch(void* const* d_in, const int* in_sizes, int n_in,
                              void* d_out, int out_size)
{
    const float* hidden = (const float*)d_in[0];
    const int*   mask   = (const int*)  d_in[1];
    const float* Wq = (const float*)d_in[2];
    const float* bq = (const float*)d_in[3];
    const float* Wk = (const float*)d_in[4];
    const float* bk = (const float*)d_in[5];
    const float* Wv = (const float*)d_in[6];
    const float* bv = (const float*)d_in[7];
    const float* Wo = (const float*)d_in[8];
    const float* bo = (const float*)d_in[9];
    float* out = (float*)d_out;

    bf16 *hh,*hl,*wqh,*wql,*wkh,*wkl,*wvh,*wvl,*woh,*wol;
    bf16 *qh,*ql,*kh,*kl,*ath,*atl;
    fp16 *v16,*vt16,*p16;
    float *scb;
    cudaGetSymbolAddress((void**)&hh,  g_hid_hi); cudaGetSymbolAddress((void**)&hl,  g_hid_lo);
    cudaGetSymbolAddress((void**)&wqh, g_wq_hi);  cudaGetSymbolAddress((void**)&wql, g_wq_lo);
    cudaGetSymbolAddress((void**)&wkh, g_wk_hi);  cudaGetSymbolAddress((void**)&wkl, g_wk_lo);
    cudaGetSymbolAddress((void**)&wvh, g_wv_hi);  cudaGetSymbolAddress((void**)&wvl, g_wv_lo);
    cudaGetSymbolAddress((void**)&woh, g_wo_hi);  cudaGetSymbolAddress((void**)&wol, g_wo_lo);
    cudaGetSymbolAddress((void**)&qh,  g_q_hi);   cudaGetSymbolAddress((void**)&ql,  g_q_lo);
    cudaGetSymbolAddress((void**)&kh,  g_k_hi);   cudaGetSymbolAddress((void**)&kl,  g_k_lo);
    cudaGetSymbolAddress((void**)&ath, g_at_hi);  cudaGetSymbolAddress((void**)&atl, g_at_lo);
    cudaGetSymbolAddress((void**)&v16, g_v_h16);
    cudaGetSymbolAddress((void**)&vt16,g_vt_h16);
    cudaGetSymbolAddress((void**)&p16, g_p_h16);
    cudaGetSymbolAddress((void**)&scb, g_scores);

    cudaFuncSetAttribute(qkv_tc,   cudaFuncAttributeMaxDynamicSharedMemorySize, SMEM3);
    cudaFuncSetAttribute(gemm_bf3, cudaFuncAttributeMaxDynamicSharedMemorySize, SMEM3);
    cudaFuncSetAttribute(gemm_pv,  cudaFuncAttributeMaxDynamicSharedMemorySize, SMEM1);

    // 0) split fp32 inputs into bf16 hi/lo planes
    {
        const int T = 256;
        int nh4 = (MROWS * DD) / 4, nw4 = (DD * DD) / 4;
        split_kernel<<<(nh4 + T - 1) / T, T>>>(hidden, hh, hl, nh4);
        split_kernel<<<(nw4 + T - 1) / T, T>>>(Wq, wqh, wql, nw4);
        split_kernel<<<(nw4 + T - 1) / T, T>>>(Wk, wkh, wkl, nw4);
        split_kernel<<<(nw4 + T - 1) / T, T>>>(Wv, wvh, wvl, nw4);
        split_kernel<<<(nw4 + T - 1) / T, T>>>(Wo, woh, wol, nw4);
    }

    // 1) Q,K,V projections (fused via grid.z): q,k -> bf16 planes; v -> fp16
    qkv_tc<<<dim3(DD / 128, MROWS / 128, 3), 512, SMEM3>>>(
        hh, hl, wqh, wql, bq, qh, ql, wkh, wkl, bk, kh, kl, wvh, wvl, bv, v16);

    // 2) V transpose (single fp16 plane)
    transpose_plane<<<dim3(SS / 32, HDIM / 32, BH), dim3(32, 8)>>>(
        (const unsigned short*)v16, (unsigned short*)vt16);

    // 3) scores = Q K^T per (b,h)  -> fp32
    gemm_bf3<<<dim3(SS / 128, SS / 128, BH), 512, SMEM3>>>(
        qh, ql, DD, (ll)SS * DD, (ll)HDIM,
        kh, kl, DD, (ll)SS * DD, (ll)HDIM,
        nullptr,
        scb, SS, (ll)16 * SS * SS, (ll)SS * SS, HDIM);

    // 4) masked softmax -> fp16 P plane
    softmax_kernel<<<BH * SS, 256>>>(scb, mask, p16);

    // 5) attn = P @ V  (fp16 single product) -> attn bf16 planes
    gemm_pv<<<dim3(HDIM / 128, SS / 128, BH), 512, SMEM1>>>(
        p16, SS, (ll)16 * SS * SS, (ll)SS * SS,
        vt16, SS, (ll)16 * HDIM * SS, (ll)HDIM * SS,
        ath, atl, DD, (ll)SS * DD, (ll)HDIM, SS);

    // 6) out = attn @ Wo^T + bo -> fp32
    gemm_bf3<<<dim3(DD / 128, MROWS / 128, 1), 512, SMEM3>>>(
        ath, atl, DD, 0, 0, woh, wol, DD, 0, 0, bo,
        out, DD, 0, 0, DD);
}

// round 6
// speedup vs baseline: 3.9189x; 1.1595x over previous
#include <cuda_runtime.h>
#include <cuda_bf16.h>
#include <cuda_fp16.h>
#include <cstdint>

#define BB 2
#define SS 2048
#define DD 2048
#define HH 16
#define HDIM 128
#define MROWS (BB*SS)     // 4096
#define BH (BB*HH)        // 32

typedef __nv_bfloat16 bf16;
typedef __half fp16;
typedef long long ll;

// ---------------------------------------------------------------------------
// Scratch (__device__ globals; cudaMalloc is forbidden)
// ---------------------------------------------------------------------------
__device__ bf16 g_hid_hi[(size_t)MROWS * DD], g_hid_lo[(size_t)MROWS * DD];
__device__ bf16 g_wq_hi [(size_t)DD * DD],    g_wq_lo [(size_t)DD * DD];
__device__ bf16 g_wk_hi [(size_t)DD * DD],    g_wk_lo [(size_t)DD * DD];
__device__ bf16 g_wv_hi [(size_t)DD * DD],    g_wv_lo [(size_t)DD * DD];
__device__ bf16 g_wo_hi [(size_t)DD * DD],    g_wo_lo [(size_t)DD * DD];
__device__ bf16 g_q_hi  [(size_t)MROWS * DD], g_q_lo  [(size_t)MROWS * DD];
__device__ bf16 g_k_hi  [(size_t)MROWS * DD], g_k_lo  [(size_t)MROWS * DD];
__device__ fp16 g_v_h16 [(size_t)MROWS * DD];
__device__ fp16 g_vt_h16[(size_t)MROWS * DD];           // [bh][128][2048]
__device__ bf16 g_at_hi [(size_t)MROWS * DD], g_at_lo [(size_t)MROWS * DD];

// ---------------------------------------------------------------------------
// mma.sync helpers (compute_80+, legal under plain sm_103 PTX target)
// ---------------------------------------------------------------------------
__device__ __forceinline__ uint32_t smem_u32_of(const void* p) {
    uint32_t a;
    asm("{ .reg .u64 t; cvta.to.shared.u64 t, %1; cvt.u32.u64 %0, t; }" : "=r"(a) : "l"(p));
    return a;
}
__device__ __forceinline__ void ldsm_x4(uint32_t* r, uint32_t addr) {
    asm volatile("ldmatrix.sync.aligned.m8n8.x4.shared.b16 {%0,%1,%2,%3}, [%4];"
                 : "=r"(r[0]), "=r"(r[1]), "=r"(r[2]), "=r"(r[3]) : "r"(addr));
}
__device__ __forceinline__ void mma_bf16(float* c, const uint32_t* a,
                                         uint32_t b0, uint32_t b1) {
    asm volatile(
        "mma.sync.aligned.m16n8k16.row.col.f32.bf16.bf16.f32 "
        "{%0,%1,%2,%3}, {%4,%5,%6,%7}, {%8,%9}, {%0,%1,%2,%3};"
        : "+f"(c[0]), "+f"(c[1]), "+f"(c[2]), "+f"(c[3])
        : "r"(a[0]), "r"(a[1]), "r"(a[2]), "r"(a[3]), "r"(b0), "r"(b1));
}
__device__ __forceinline__ void mma_fp16(float* c, const uint32_t* a,
                                         uint32_t b0, uint32_t b1) {
    asm volatile(
        "mma.sync.aligned.m16n8k16.row.col.f32.f16.f16.f32 "
        "{%0,%1,%2,%3}, {%4,%5,%6,%7}, {%8,%9}, {%0,%1,%2,%3};"
        : "+f"(c[0]), "+f"(c[1]), "+f"(c[2]), "+f"(c[3])
        : "r"(a[0]), "r"(a[1]), "r"(a[2]), "r"(a[3]), "r"(b0), "r"(b1));
}
__device__ __forceinline__ uint32_t pack_hi2(float x, float y) {
    bf16 a = __float2bfloat16_rn(x), b = __float2bfloat16_rn(y);
    return (uint32_t)__bfloat16_as_ushort(a) | ((uint32_t)__bfloat16_as_ushort(b) << 16);
}
__device__ __forceinline__ uint32_t pack_lo2(float x, float y) {
    bf16 a = __float2bfloat16_rn(x), b = __float2bfloat16_rn(y);
    bf16 c = __float2bfloat16_rn(x - __bfloat162float(a));
    bf16 d = __float2bfloat16_rn(y - __bfloat162float(b));
    return (uint32_t)__bfloat16_as_ushort(c) | ((uint32_t)__bfloat16_as_ushort(d) << 16);
}
__device__ __forceinline__ uint32_t pack_f16_2(float x, float y) {
    __half2 h = __floats2half2_rn(x, y);
    return *(uint32_t*)&h;
}

// ---------------------------------------------------------------------------
// Split pass: fp32 tensor -> bf16 hi/lo planes
// ---------------------------------------------------------------------------
__global__ void split_kernel(const float* __restrict__ src,
                             bf16* __restrict__ hi, bf16* __restrict__ lo, int n4)
{
    int i = blockIdx.x * blockDim.x + threadIdx.x;
    if (i >= n4) return;
    float4 v = ((const float4*)src)[i];
    ((uint2*)hi)[i] = make_uint2(pack_hi2(v.x, v.y), pack_hi2(v.z, v.w));
    ((uint2*)lo)[i] = make_uint2(pack_lo2(v.x, v.y), pack_lo2(v.z, v.w));
}

// ---------------------------------------------------------------------------
// Projection GEMM (bf16 3-product): block tile 128x128, k-tile 64, 512 thr.
// ---------------------------------------------------------------------------
#define BKT 64
#define ROWB 144
#define TILEB (128*ROWB)           // 18432
#define S3_STAGE (4*TILEB)         // 73728 (Ahi,Alo,Bhi,Blo)
#define SMEM3 (2*S3_STAGE)         // 147456

// outmode: 0 = fp32 D, 1 = bf16 hi/lo planes, 2 = fp16 plane
__device__ __forceinline__ void epilogue_store(
    int outmode, const float* bias,
    float* D, bf16* Dhi, bf16* Dlo, fp16* Dh16, int ldd,
    int bm, int bn, int wm, int wn, int lane, float acc[2][4][4])
{
    const int er = lane >> 2;
    const int ec = (lane & 3) * 2;
#pragma unroll
    for (int mf = 0; mf < 2; mf++) {
#pragma unroll
        for (int nf = 0; nf < 4; nf++) {
            int gr = bm + wm + mf * 16 + er;
            int gc = bn + wn + nf * 8 + ec;
            float b0 = 0.f, b1 = 0.f;
            if (bias) { b0 = bias[gc]; b1 = bias[gc + 1]; }
            float x0 = acc[mf][nf][0] + b0, x1 = acc[mf][nf][1] + b1;
            float x2 = acc[mf][nf][2] + b0, x3 = acc[mf][nf][3] + b1;
            size_t o0 = (size_t)gr * ldd + gc;
            size_t o1 = (size_t)(gr + 8) * ldd + gc;
            if (outmode == 0) {
                *(float2*)(D + o0) = make_float2(x0, x1);
                *(float2*)(D + o1) = make_float2(x2, x3);
            } else if (outmode == 1) {
                *(uint32_t*)(Dhi + o0) = pack_hi2(x0, x1);
                *(uint32_t*)(Dlo + o0) = pack_lo2(x0, x1);
                *(uint32_t*)(Dhi + o1) = pack_hi2(x2, x3);
                *(uint32_t*)(Dlo + o1) = pack_lo2(x2, x3);
            } else {
                *(uint32_t*)(Dh16 + o0) = pack_f16_2(x0, x1);
                *(uint32_t*)(Dh16 + o1) = pack_f16_2(x2, x3);
            }
        }
    }
}

__device__ __forceinline__ void gemm_bf3_body(
    const bf16* __restrict__ Ahi, const bf16* __restrict__ Alo, int lda,
    const bf16* __restrict__ Bhi, const bf16* __restrict__ Blo, int ldb,
    const float* __restrict__ bias,
    float* __restrict__ D, bf16* __restrict__ Dhi, bf16* __restrict__ Dlo,
    fp16* __restrict__ Dh16, int ldd, int K, int outmode)
{
    extern __shared__ __align__(1024) char smem[];
    const uint32_t sbase = smem_u32_of(smem);

    const int tid  = threadIdx.x;
    const int wid  = tid >> 5;
    const int lane = tid & 31;
    const int wm = (wid >> 2) * 32;
    const int wn = (wid & 3)  * 32;
    const int bm = blockIdx.y * 128;
    const int bn = blockIdx.x * 128;

    float acc[2][4][4];
#pragma unroll
    for (int mf = 0; mf < 2; mf++)
#pragma unroll
        for (int nf = 0; nf < 4; nf++)
#pragma unroll
            for (int e = 0; e < 4; e++) acc[mf][nf][e] = 0.f;

    const bf16* srcA[2] = { Ahi + (size_t)bm * lda, Alo + (size_t)bm * lda };
    const bf16* srcB[2] = { Bhi + (size_t)bn * ldb, Blo + (size_t)bn * ldb };

    uint4 streg[8];
    auto gload = [&](int kt) {
#pragma unroll
        for (int i = 0; i < 8; i++) {
            int slot = tid + i * 512;
            int tile = slot >> 10;
            int r    = (slot >> 3) & 127;
            int c8   = slot & 7;
            const bf16* gp = (tile < 2)
                ? srcA[tile]     + (size_t)r * lda + kt * BKT + c8 * 8
                : srcB[tile - 2] + (size_t)r * ldb + kt * BKT + c8 * 8;
            streg[i] = *(const uint4*)gp;
        }
    };
    auto sstore = [&](int s) {
        char* st = smem + s * S3_STAGE;
#pragma unroll
        for (int i = 0; i < 8; i++) {
            int slot = tid + i * 512;
            int tile = slot >> 10;
            int r    = (slot >> 3) & 127;
            int c8   = slot & 7;
            *(uint4*)(st + tile * TILEB + r * ROWB + c8 * 16) = streg[i];
        }
    };

    const int NKT = K / BKT;
    gload(0);
    sstore(0);
    __syncthreads();

    const int a_row  = lane & 15;
    const int a_colB = (lane >> 4) * 16;
    const int b_row  = (lane & 7) + ((lane & 16) ? 8 : 0);
    const int b_colB = (lane & 8) ? 16 : 0;

    for (int kt = 0; kt < NKT; kt++) {
        const int s = kt & 1;
        if (kt + 1 < NKT) gload(kt + 1);

        const uint32_t sb = sbase + s * S3_STAGE;
#pragma unroll
        for (int ks = 0; ks < 4; ks++) {
            uint32_t ah[2][4], al[2][4], bh[2][4], bl[2][4];
            const int kB = ks * 32;
#pragma unroll
            for (int mf = 0; mf < 2; mf++) {
                uint32_t ad = sb + (wm + mf * 16 + a_row) * ROWB + a_colB + kB;
                ldsm_x4(ah[mf], ad);
                ldsm_x4(al[mf], ad + TILEB);
            }
#pragma unroll
            for (int np = 0; np < 2; np++) {
                uint32_t bd = sb + 2 * TILEB + (wn + np * 16 + b_row) * ROWB + b_colB + kB;
                ldsm_x4(bh[np], bd);
                ldsm_x4(bl[np], bd + TILEB);
            }
#pragma unroll
            for (int mf = 0; mf < 2; mf++)
#pragma unroll
                for (int np = 0; np < 2; np++)
#pragma unroll
                    for (int h = 0; h < 2; h++) {
                        int nf = np * 2 + h;
                        mma_bf16(acc[mf][nf], ah[mf], bh[np][2*h], bh[np][2*h+1]);
                        mma_bf16(acc[mf][nf], ah[mf], bl[np][2*h], bl[np][2*h+1]);
                        mma_bf16(acc[mf][nf], al[mf], bh[np][2*h], bh[np][2*h+1]);
                    }
        }
        if (kt + 1 < NKT) sstore((kt + 1) & 1);
        __syncthreads();
    }

    epilogue_store(outmode, bias, D, Dhi, Dlo, Dh16, ldd, bm, bn, wm, wn, lane, acc);
}

__global__ __launch_bounds__(512, 1) void gemm_bf3(
    const bf16* Ahi, const bf16* Alo, int lda,
    const bf16* Bhi, const bf16* Blo, int ldb,
    const float* bias, float* D, int ldd, int K)
{
    gemm_bf3_body(Ahi, Alo, lda, Bhi, Blo, ldb, bias,
                  D, nullptr, nullptr, nullptr, ldd, K, 0);
}

// Fused QKV: z in {0,1}: bf16 planes out (q,k); z==2: fp16 plane out (v)
__global__ __launch_bounds__(512, 1) void qkv_tc(
    const bf16* hhi, const bf16* hlo,
    const bf16* wqh, const bf16* wql, const float* bq, bf16* qhi, bf16* qlo,
    const bf16* wkh, const bf16* wkl, const float* bk, bf16* khi, bf16* klo,
    const bf16* wvh, const bf16* wvl, const float* bv, fp16* vh16)
{
    if (blockIdx.z == 0)
        gemm_bf3_body(hhi, hlo, DD, wqh, wql, DD, bq, nullptr, qhi, qlo, nullptr, DD, DD, 1);
    else if (blockIdx.z == 1)
        gemm_bf3_body(hhi, hlo, DD, wkh, wkl, DD, bk, nullptr, khi, klo, nullptr, DD, DD, 1);
    else
        gemm_bf3_body(hhi, hlo, DD, wvh, wvl, DD, bv, nullptr, nullptr, nullptr, vh16, DD, DD, 2);
}

// ---------------------------------------------------------------------------
// Transpose of a 16-bit plane: v[(b,s), h*128+d] -> vt[(bh*128+d), s]
// ---------------------------------------------------------------------------
__global__ void transpose_plane(const unsigned short* __restrict__ vs,
                                unsigned short* __restrict__ vd)
{
    __shared__ unsigned short t[32][36];
    const int bh = blockIdx.z;
    const int b = bh >> 4, h = bh & 15;
    const int s0 = blockIdx.x * 32, d0 = blockIdx.y * 32;
    const int tx = threadIdx.x, ty = threadIdx.y;
#pragma unroll
    for (int i = 0; i < 32; i += 8)
        t[ty + i][tx] = vs[(size_t)(b * SS + s0 + ty + i) * DD + h * HDIM + d0 + tx];
    __syncthreads();
#pragma unroll
    for (int i = 0; i < 32; i += 8)
        vd[(size_t)(bh * HDIM + d0 + ty + i) * SS + s0 + tx] = t[tx][ty + i];
}

// ---------------------------------------------------------------------------
// Fused flash attention: scores (bf16 3-product) + online softmax + PV (fp16).
// Block = 128 q-rows of one (b,h); 8 warps x 16 rows; 64-key tiles,
// double-buffered K (hi/lo) + V^T; Q resident in smem.
// Output: attn written as bf16 hi/lo planes.
// ---------------------------------------------------------------------------
#define QROWB 272               // 128 bf16 * 2B + 16 pad
#define KROWB 272
#define VROWB 144               // 64 fp16 * 2B + 16 pad
#define FA_QPLANE (128*QROWB)   // 34816
#define FA_QBYTES (2*FA_QPLANE) // 69632
#define FA_KHI 0
#define FA_KLO (64*KROWB)       // 17408
#define FA_V   (2*64*KROWB)     // 34816
#define FA_MSK (FA_V + 128*VROWB)   // 53248
#define FA_STG (FA_MSK + 256)       // 53504
#define FA_SMEM (FA_QBYTES + 2*FA_STG)  // 176640

__global__ __launch_bounds__(256, 1) void fused_attn(
    const bf16* __restrict__ qh, const bf16* __restrict__ ql,
    const bf16* __restrict__ kh, const bf16* __restrict__ kl,
    const fp16* __restrict__ vt, const int* __restrict__ mask,
    bf16* __restrict__ ath, bf16* __restrict__ atl)
{
    extern __shared__ __align__(1024) char smem[];
    const uint32_t sbase = smem_u32_of(smem);

    const int tid  = threadIdx.x;
    const int wid  = tid >> 5;
    const int lane = tid & 31;
    const int bh   = blockIdx.y;
    const int b    = bh >> 4, h = bh & 15;
    const int q0   = blockIdx.x * 128;
    const int wm   = wid * 16;              // warp's q-row base within tile
    const float scale = 0.08838834764831845f;

    // --- load Q tile (hi/lo) into smem ---
    {
        const size_t gbase = (size_t)(b * SS + q0) * DD + h * HDIM;
#pragma unroll
        for (int i = 0; i < 8; i++) {
            int slot = tid + i * 256;        // 0..2047
            int r = slot >> 4, c8 = slot & 15;
            *(uint4*)(smem + r * QROWB + c8 * 16) =
                *(const uint4*)(qh + gbase + (size_t)r * DD + c8 * 8);
            *(uint4*)(smem + FA_QPLANE + r * QROWB + c8 * 16) =
                *(const uint4*)(ql + gbase + (size_t)r * DD + c8 * 8);
        }
    }

    // --- K/V/mask tile staging (double-buffered) ---
    const size_t kgbase = (size_t)(b * SS) * DD + h * HDIM;
    const size_t vgbase = (size_t)bh * HDIM * SS;
    uint4 streg[12];
    int4 mreg;
    auto gload = [&](int kt) {
        const int k0 = kt * 64;
#pragma unroll
        for (int i = 0; i < 12; i++) {
            int slot = tid + i * 256;        // 0..3071
            if (slot < 2048) {               // Khi / Klo: 64 rows x 16 c8
                int r = (slot & 1023) >> 4, c8 = slot & 15;
                const bf16* src = (slot < 1024) ? kh : kl;
                streg[i] = *(const uint4*)(src + kgbase + (size_t)(k0 + r) * DD + c8 * 8);
            } else {                         // V^T: 128 rows x 8 c8
                int j = slot - 2048;
                int r = j >> 3, c8 = j & 7;
                streg[i] = *(const uint4*)(vt + vgbase + (size_t)r * SS + k0 + c8 * 8);
            }
        }
        if (tid < 16) mreg = *(const int4*)(mask + b * SS + k0 + tid * 4);
    };
    auto sstore = [&](int s) {
        char* st = smem + FA_QBYTES + s * FA_STG;
#pragma unroll
        for (int i = 0; i < 12; i++) {
            int slot = tid + i * 256;
            if (slot < 2048) {
                int r = (slot & 1023) >> 4, c8 = slot & 15;
                int off = (slot < 1024) ? FA_KHI : FA_KLO;
                *(uint4*)(st + off + r * KROWB + c8 * 16) = streg[i];
            } else {
                int j = slot - 2048;
                int r = j >> 3, c8 = j & 7;
                *(uint4*)(st + FA_V + r * VROWB + c8 * 16) = streg[i];
            }
        }
        if (tid < 16) *(int4*)(st + FA_MSK + tid * 16) = mreg;
    };

    // --- state ---
    float m_run[2] = {-1e30f, -1e30f};
    float l_run[2] = {0.f, 0.f};
    float oacc[16][4];
#pragma unroll
    for (int nf = 0; nf < 16; nf++)
#pragma unroll
        for (int e = 0; e < 4; e++) oacc[nf][e] = 0.f;

    const int a_row  = lane & 15;
    const int a_sel  = (lane >> 4) * 16;
    const int b_row  = (lane & 7) + ((lane & 16) ? 8 : 0);
    const int b_sel  = (lane & 8) ? 16 : 0;

    gload(0);
    sstore(0);
    __syncthreads();

    const int NKT = SS / 64;   // 32
    for (int kt = 0; kt < NKT; kt++) {
        const int s = kt & 1;
        if (kt + 1 < NKT) gload(kt + 1);

        const uint32_t stg = sbase + FA_QBYTES + s * FA_STG;

        // ---- S = Q K^T (16 x 64 per warp, bf16 3-product) ----
        float sacc[8][4];
#pragma unroll
        for (int nf = 0; nf < 8; nf++)
#pragma unroll
            for (int e = 0; e < 4; e++) sacc[nf][e] = 0.f;

#pragma unroll
        for (int ks = 0; ks < 8; ks++) {
            const int kB = ks * 32;
            uint32_t ah[4], al_[4];
            uint32_t qaddr = sbase + (wm + a_row) * QROWB + a_sel + kB;
            ldsm_x4(ah, qaddr);
            ldsm_x4(al_, qaddr + FA_QPLANE);
#pragma unroll
            for (int np = 0; np < 4; np++) {
                uint32_t bh_[4], bl_[4];
                uint32_t kaddr = stg + FA_KHI + (np * 16 + b_row) * KROWB + b_sel + kB;
                ldsm_x4(bh_, kaddr);
                ldsm_x4(bl_, kaddr + (FA_KLO - FA_KHI));
#pragma unroll
                for (int hh = 0; hh < 2; hh++) {
                    int nf = np * 2 + hh;
                    mma_bf16(sacc[nf], ah,  bh_[2*hh], bh_[2*hh+1]);
                    mma_bf16(sacc[nf], ah,  bl_[2*hh], bl_[2*hh+1]);
                    mma_bf16(sacc[nf], al_, bh_[2*hh], bh_[2*hh+1]);
                }
            }
        }

        // ---- mask + scale ----
        const int* msk = (const int*)(smem + FA_QBYTES + s * FA_STG + FA_MSK);
        const int mc = (lane & 3) * 2;
#pragma unroll
        for (int nf = 0; nf < 8; nf++) {
            int c0 = nf * 8 + mc;
            bool m0 = msk[c0] != 0, m1 = msk[c0 + 1] != 0;
            sacc[nf][0] = m0 ? sacc[nf][0] * scale : -1e9f;
            sacc[nf][1] = m1 ? sacc[nf][1] * scale : -1e9f;
            sacc[nf][2] = m0 ? sacc[nf][2] * scale : -1e9f;
            sacc[nf][3] = m1 ? sacc[nf][3] * scale : -1e9f;
        }

        // ---- online softmax (rows: lane>>2 and +8; quad = 4 lanes/row) ----
        float tmax[2] = {-1e30f, -1e30f};
#pragma unroll
        for (int nf = 0; nf < 8; nf++) {
            tmax[0] = fmaxf(tmax[0], fmaxf(sacc[nf][0], sacc[nf][1]));
            tmax[1] = fmaxf(tmax[1], fmaxf(sacc[nf][2], sacc[nf][3]));
        }
#pragma unroll
        for (int o = 1; o <= 2; o <<= 1) {
            tmax[0] = fmaxf(tmax[0], __shfl_xor_sync(~0u, tmax[0], o));
            tmax[1] = fmaxf(tmax[1], __shfl_xor_sync(~0u, tmax[1], o));
        }
        float mnew0 = fmaxf(m_run[0], tmax[0]);
        float mnew1 = fmaxf(m_run[1], tmax[1]);
        float alpha0 = __expf(m_run[0] - mnew0);
        float alpha1 = __expf(m_run[1] - mnew1);
        m_run[0] = mnew0; m_run[1] = mnew1;

        float rs0 = 0.f, rs1 = 0.f;
        uint32_t pa[4][4];
#pragma unroll
        for (int np = 0; np < 4; np++) {
            float p00, p01, p10, p11, q00, q01, q10, q11;
            {
                int nf = 2 * np;
                p00 = __expf(sacc[nf][0] - mnew0);
                p01 = __expf(sacc[nf][1] - mnew0);
                p10 = __expf(sacc[nf][2] - mnew1);
                p11 = __expf(sacc[nf][3] - mnew1);
            }
            {
                int nf = 2 * np + 1;
                q00 = __expf(sacc[nf][0] - mnew0);
                q01 = __expf(sacc[nf][1] - mnew0);
                q10 = __expf(sacc[nf][2] - mnew1);
                q11 = __expf(sacc[nf][3] - mnew1);
            }
            rs0 += p00 + p01 + q00 + q01;
            rs1 += p10 + p11 + q10 + q11;
            pa[np][0] = pack_f16_2(p00, p01);   // row lane>>2,  k 0..7 of this 16
            pa[np][1] = pack_f16_2(p10, p11);   // row +8
            pa[np][2] = pack_f16_2(q00, q01);   // k 8..15
            pa[np][3] = pack_f16_2(q10, q11);
        }
#pragma unroll
        for (int o = 1; o <= 2; o <<= 1) {
            rs0 += __shfl_xor_sync(~0u, rs0, o);
            rs1 += __shfl_xor_sync(~0u, rs1, o);
        }
        l_run[0] = l_run[0] * alpha0 + rs0;
        l_run[1] = l_run[1] * alpha1 + rs1;
#pragma unroll
        for (int nf = 0; nf < 16; nf++) {
            oacc[nf][0] *= alpha0; oacc[nf][1] *= alpha0;
            oacc[nf][2] *= alpha1; oacc[nf][3] *= alpha1;
        }

        // ---- O += P V  (fp16, P from registers, V^T from smem) ----
#pragma unroll
        for (int t = 0; t < 4; t++) {
            const int kB = t * 32;
#pragma unroll
            for (int nh = 0; nh < 8; nh++) {
                uint32_t bv[4];
                ldsm_x4(bv, stg + FA_V + (nh * 16 + b_row) * VROWB + b_sel + kB);
                mma_fp16(oacc[2*nh],     pa[t], bv[0], bv[1]);
                mma_fp16(oacc[2*nh + 1], pa[t], bv[2], bv[3]);
            }
        }

        if (kt + 1 < NKT) sstore((kt + 1) & 1);
        __syncthreads();
    }

    // ---- epilogue: normalize, write bf16 hi/lo planes ----
    const float inv0 = 1.f / l_run[0];
    const float inv1 = 1.f / l_run[1];
    const int er = lane >> 2;
    const int ec = (lane & 3) * 2;
    const size_t obase = (size_t)(b * SS + q0 + wm) * DD + h * HDIM;
#pragma unroll
    for (int nf = 0; nf < 16; nf++) {
        int gc = nf * 8 + ec;
        float x0 = oacc[nf][0] * inv0, x1 = oacc[nf][1] * inv0;
        float x2 = oacc[nf][2] * inv1, x3 = oacc[nf][3] * inv1;
        size_t o0 = obase + (size_t)er * DD + gc;
        size_t o1 = obase + (size_t)(er + 8) * DD + gc;
        *(uint32_t*)(ath + o0) = pack_hi2(x0, x1);
        *(uint32_t*)(atl + o0) = pack_lo2(x0, x1);
        *(uint32_t*)(ath + o1) = pack_hi2(x2, x3);
        *(uint32_t*)(atl + o1) = pack_lo2(x2, x3);
    }
}

// ---------------------------------------------------------------------------
extern "C" void kernel_launch(void* const* d_in, const int* in_sizes, int n_in,
                              void* d_out, int out_size)
{
    const float* hidden = (const float*)d_in[0];
    const int*   mask   = (const int*)  d_in[1];
    const float* Wq = (const float*)d_in[2];
    const float* bq = (const float*)d_in[3];
    const float* Wk = (const float*)d_in[4];
    const float* bk = (const float*)d_in[5];
    const float* Wv = (const float*)d_in[6];
    const float* bv = (const float*)d_in[7];
    const float* Wo = (const float*)d_in[8];
    const float* bo = (const float*)d_in[9];
    float* out = (float*)d_out;

    bf16 *hh,*hl,*wqh,*wql,*wkh,*wkl,*wvh,*wvl,*woh,*wol;
    bf16 *qh,*ql,*kh,*kl,*ath,*atl;
    fp16 *v16,*vt16;
    cudaGetSymbolAddress((void**)&hh,  g_hid_hi); cudaGetSymbolAddress((void**)&hl,  g_hid_lo);
    cudaGetSymbolAddress((void**)&wqh, g_wq_hi);  cudaGetSymbolAddress((void**)&wql, g_wq_lo);
    cudaGetSymbolAddress((void**)&wkh, g_wk_hi);  cudaGetSymbolAddress((void**)&wkl, g_wk_lo);
    cudaGetSymbolAddress((void**)&wvh, g_wv_hi);  cudaGetSymbolAddress((void**)&wvl, g_wv_lo);
    cudaGetSymbolAddress((void**)&woh, g_wo_hi);  cudaGetSymbolAddress((void**)&wol, g_wo_lo);
    cudaGetSymbolAddress((void**)&qh,  g_q_hi);   cudaGetSymbolAddress((void**)&ql,  g_q_lo);
    cudaGetSymbolAddress((void**)&kh,  g_k_hi);   cudaGetSymbolAddress((void**)&kl,  g_k_lo);
    cudaGetSymbolAddress((void**)&ath, g_at_hi);  cudaGetSymbolAddress((void**)&atl, g_at_lo);
    cudaGetSymbolAddress((void**)&v16, g_v_h16);
    cudaGetSymbolAddress((void**)&vt16,g_vt_h16);

    cudaFuncSetAttribute(qkv_tc,     cudaFuncAttributeMaxDynamicSharedMemorySize, SMEM3);
    cudaFuncSetAttribute(gemm_bf3,   cudaFuncAttributeMaxDynamicSharedMemorySize, SMEM3);
    cudaFuncSetAttribute(fused_attn, cudaFuncAttributeMaxDynamicSharedMemorySize, FA_SMEM);

    // 0) split fp32 inputs into bf16 hi/lo planes
    {
        const int T = 256;
        int nh4 = (MROWS * DD) / 4, nw4 = (DD * DD) / 4;
        split_kernel<<<(nh4 + T - 1) / T, T>>>(hidden, hh, hl, nh4);
        split_kernel<<<(nw4 + T - 1) / T, T>>>(Wq, wqh, wql, nw4);
        split_kernel<<<(nw4 + T - 1) / T, T>>>(Wk, wkh, wkl, nw4);
        split_kernel<<<(nw4 + T - 1) / T, T>>>(Wv, wvh, wvl, nw4);
        split_kernel<<<(nw4 + T - 1) / T, T>>>(Wo, woh, wol, nw4);
    }

    // 1) Q,K,V projections (fused via grid.z): q,k -> bf16 planes; v -> fp16
    qkv_tc<<<dim3(DD / 128, MROWS / 128, 3), 512, SMEM3>>>(
        hh, hl, wqh, wql, bq, qh, ql, wkh, wkl, bk, kh, kl, wvh, wvl, bv, v16);

    // 2) V transpose (single fp16 plane)
    transpose_plane<<<dim3(SS / 32, HDIM / 32, BH), dim3(32, 8)>>>(
        (const unsigned short*)v16, (unsigned short*)vt16);

    // 3) fused attention: scores + softmax + PV -> attn bf16 planes
    fused_attn<<<dim3(SS / 128, BH), 256, FA_SMEM>>>(
        qh, ql, kh, kl, vt16, mask, ath, atl);

    // 4) out = attn @ Wo^T + bo -> fp32
    gemm_bf3<<<dim3(DD / 128, MROWS / 128, 1), 512, SMEM3>>>(
        ath, atl, DD, woh, wol, DD, bo, out, DD, DD);
}